// round 3
// baseline (speedup 1.0000x reference)
#include <cuda_runtime.h>

// Problem dims
// x:    (8, 576, 56, 56)  fp32   14,450,688 elems
// fc_w: (1728, 576)       fp32      995,328 elems
// w1:   (9, 192, 3, 3, 3) fp32       46,656 elems
// w2:   (9, 192, 3, 3)    fp32       15,552 elems
// out:  (8, 192, 56, 56)  fp32

#define B_SZ 8
#define CIN 576
#define C_OUT 192
#define KK 9
#define H_IMG 56
#define W_IMG 56
#define HW 3136

// ---------------------------------------------------------------------------
// Single fully-fused naive kernel. One block = (b, c, 28x28 spatial tile).
// Everything computed from first principles:
//   logits[i](p) = sum_cin fc_w[c*9+i][cin] * x[b][cin][p]      (inline GEMV)
//   attn = softmax_i(logits)
//   feat_i(y,x)  = relu( sum_{j,kh,kw} w1[i,c,j,kh,kw] * x[b][3c+j][y-1+kh][x-1+kw] )
//   out(p)       = sum_i attn_i(p) * sum_{kh,kw} w2[i,c,kh,kw] * feat_i(p +- 1)
// feat is recomputed per output pixel (9x redundancy) -- correctness first.
// ---------------------------------------------------------------------------
__global__ __launch_bounds__(256)
void dynconv_naive_kernel(const float* __restrict__ x,
                          const float* __restrict__ fc_w,
                          const float* __restrict__ w1,
                          const float* __restrict__ w2,
                          float* __restrict__ out)
{
    __shared__ float xs[3][32][32];      // x channels 3c..3c+2, tile + halo 2
    __shared__ float fcs[9][CIN];        // fc_w rows c*9 .. c*9+8  (20736 B)
    __shared__ float w1s[9][27];
    __shared__ float w2s[9][9];

    const int bc  = blockIdx.z;
    const int b   = bc / C_OUT;
    const int c   = bc % C_OUT;
    const int ty0 = blockIdx.y * 28;
    const int tx0 = blockIdx.x * 28;
    const int tid = threadIdx.x;

    // --- stage fc_w rows for this channel: rows o = c*9+i ---
    for (int e = tid; e < 9 * CIN; e += 256) {
        const int i   = e / CIN;
        const int cin = e - i * CIN;
        fcs[i][cin] = fc_w[(size_t)(c * KK + i) * CIN + cin];
    }
    // --- stage w1: w1[i, c, j, kh, kw], flat = i*(192*27) + c*27 + r ---
    for (int e = tid; e < 243; e += 256) {
        const int i = e / 27;
        const int r = e - i * 27;
        w1s[i][r] = w1[(size_t)i * (C_OUT * 27) + c * 27 + r];
    }
    // --- stage w2: w2[i, c, kh, kw], flat = i*(192*9) + c*9 + r ---
    for (int e = tid; e < 81; e += 256) {
        const int i = e / 9;
        const int r = e - i * 9;
        w2s[i][r] = w2[(size_t)i * (C_OUT * 9) + c * 9 + r];
    }
    // --- stage x tile (3 channels, 32x32 with halo 2, zero outside image) ---
    const float* xb = x + ((size_t)b * CIN + 3 * c) * HW;
    for (int e = tid; e < 3 * 32 * 32; e += 256) {
        const int j  = e >> 10;
        const int r  = e & 1023;
        const int ly = r >> 5;
        const int lx = r & 31;
        const int gy = ty0 - 2 + ly;
        const int gx = tx0 - 2 + lx;
        float v = 0.f;
        if ((unsigned)gy < (unsigned)H_IMG && (unsigned)gx < (unsigned)W_IMG)
            v = xb[(size_t)j * HW + gy * W_IMG + gx];
        xs[j][ly][lx] = v;
    }
    __syncthreads();

    const float* xcol = x + (size_t)b * CIN * HW;   // x[b][cin][p] = xcol[cin*HW + p]
    float* ob = out + ((size_t)b * C_OUT + c) * HW;

    for (int e = tid; e < 28 * 28; e += 256) {
        const int oy = e / 28;
        const int ox = e - oy * 28;
        const int gy = ty0 + oy;
        const int gx = tx0 + ox;
        const int p  = gy * W_IMG + gx;

        // ---- inline logits: 9 dot products of length 576 ----
        float l[9];
#pragma unroll
        for (int i = 0; i < 9; i++) l[i] = 0.f;
        const float* xp = xcol + p;
        for (int cin = 0; cin < CIN; cin++) {
            const float xv = xp[(size_t)cin * HW];
#pragma unroll
            for (int i = 0; i < 9; i++)
                l[i] = fmaf(fcs[i][cin], xv, l[i]);
        }

        // ---- softmax over the 9 kernel positions ----
        float mx = l[0];
#pragma unroll
        for (int i = 1; i < 9; i++) mx = fmaxf(mx, l[i]);
        float s = 0.f;
#pragma unroll
        for (int i = 0; i < 9; i++) {
            l[i] = expf(l[i] - mx);
            s += l[i];
        }
        const float inv = 1.f / s;

        // ---- per position: depthwise conv over on-the-fly feat, weighted sum ----
        float acc = 0.f;
#pragma unroll
        for (int i = 0; i < 9; i++) {
            float dw = 0.f;
#pragma unroll
            for (int kh = 0; kh < 3; kh++) {
#pragma unroll
                for (int kw = 0; kw < 3; kw++) {
                    // feat point at global (fgy, fgx); zero if outside image
                    const int fgy = gy - 1 + kh;
                    const int fgx = gx - 1 + kw;
                    float fv = 0.f;
                    if ((unsigned)fgy < (unsigned)H_IMG &&
                        (unsigned)fgx < (unsigned)W_IMG) {
                        // conv1 at this feat point from xs.
                        // x row  = fgy - 1 + k2h  -> local ly = oy + kh + k2h  (0..31)
                        // x col  = fgx - 1 + k2w  -> local lx = ox + kw + k2w  (0..31)
                        float a = 0.f;
#pragma unroll
                        for (int j = 0; j < 3; j++)
#pragma unroll
                            for (int k2h = 0; k2h < 3; k2h++)
#pragma unroll
                                for (int k2w = 0; k2w < 3; k2w++)
                                    a = fmaf(w1s[i][j * 9 + k2h * 3 + k2w],
                                             xs[j][oy + kh + k2h][ox + kw + k2w],
                                             a);
                        fv = fmaxf(a, 0.f);
                    }
                    dw = fmaf(w2s[i][kh * 3 + kw], fv, dw);
                }
            }
            acc = fmaf(l[i] * inv, dw, acc);
        }
        ob[p] = acc;
    }
}

// ---------------------------------------------------------------------------
extern "C" void kernel_launch(void* const* d_in, const int* in_sizes, int n_in,
                              void* d_out, int out_size)
{
    // Bind inputs by element count (robust to metadata ordering):
    const float* x    = nullptr;
    const float* fc_w = nullptr;
    const float* w1   = nullptr;
    const float* w2   = nullptr;
    for (int i = 0; i < n_in; i++) {
        switch (in_sizes[i]) {
            case B_SZ * CIN * HW:            x    = (const float*)d_in[i]; break; // 14450688
            case C_OUT * KK * CIN:           fc_w = (const float*)d_in[i]; break; // 995328
            case KK * C_OUT * 3 * 3 * 3:     w1   = (const float*)d_in[i]; break; // 46656
            case KK * C_OUT * 3 * 3:         w2   = (const float*)d_in[i]; break; // 15552
            default: break;
        }
    }
    float* out = (float*)d_out;

    dim3 grid(2, 2, B_SZ * C_OUT);   // 2x2 spatial tiles x 1536 (b,c) pairs
    dynconv_naive_kernel<<<grid, 256>>>(x, fc_w, w1, w2, out);
}

// round 4
// speedup vs baseline: 1.6470x; 1.6470x over previous
#include <cuda_runtime.h>

// Problem dims
// x:    (8, 576, 56, 56)  fp32   14,450,688 elems
// fc_w: (1728, 576)       fp32      995,328 elems
// w1:   (9, 192, 3, 3, 3) fp32       46,656 elems
// w2:   (9, 192, 3, 3)    fp32       15,552 elems
// out:  (8, 192, 56, 56)  fp32

#define B_SZ 8
#define CIN 576
#define C_OUT 192
#define KK 9
#define H_IMG 56
#define W_IMG 56
#define HW 3136

#define NTHREADS 224      // 7 warps; 196 own one float4 pixel-group each
#define NGROUPS 196       // 28x28 tile = 784 px = 196 float4 groups (7 per row)

// ---------------------------------------------------------------------------
// Single fused kernel, one block = (b, c, 28x28 spatial tile).
// Phase A: logits GEMV, register-tiled: thread owns 4 consecutive pixels,
//          accumulates 9 logits x 4 px in regs. fc weights in smem [cin][12].
// Phase B: conv1+ReLU feat tile (9 x 30x30) into smem (computed once).
// Phase C: per pixel softmax + depthwise conv2 + weighted sum, float4 store.
// fc-weight smem and feat smem share one pool (disjoint lifetimes).
// ---------------------------------------------------------------------------
__global__ __launch_bounds__(NTHREADS)
void dynconv_fused_kernel(const float* __restrict__ x,
                          const float* __restrict__ fc_w,
                          const float* __restrict__ w1,
                          const float* __restrict__ w2,
                          float* __restrict__ out)
{
    __shared__ float pool[8100];        // max(fcs_t 576*12=6912, fs 9*900=8100)
    __shared__ float xs[3][32][32];     // x channels 3c..3c+2, tile + halo 2
    __shared__ float w1s[9][27];
    __shared__ float w2s[9][9];

    float (*fcs_t)[12] = reinterpret_cast<float (*)[12]>(pool);   // [576][12]
    float*  fs = pool;                                             // [9][30][30]

    const int bc  = blockIdx.z;
    const int b   = bc / C_OUT;
    const int c   = bc % C_OUT;
    const int ty0 = blockIdx.y * 28;
    const int tx0 = blockIdx.x * 28;
    const int tid = threadIdx.x;

    // ---- stage fc weights transposed: fcs_t[cin][i] = fc_w[c*9+i][cin] ----
    for (int e = tid; e < 9 * CIN; e += NTHREADS) {
        const int i   = e / CIN;       // coalesced over cin for fixed i
        const int cin = e - i * CIN;
        fcs_t[cin][i] = fc_w[(size_t)(c * KK + i) * CIN + cin];
    }
    // ---- stage w1, w2 ----
    for (int e = tid; e < 243; e += NTHREADS)
        w1s[e / 27][e % 27] = w1[(size_t)(e / 27) * (C_OUT * 27) + c * 27 + (e % 27)];
    for (int e = tid; e < 81; e += NTHREADS)
        w2s[e / 9][e % 9] = w2[(size_t)(e / 9) * (C_OUT * 9) + c * 9 + (e % 9)];
    // ---- stage x tile (3 ch, 32x32, halo 2, zero outside) ----
    const float* xb = x + ((size_t)b * CIN + 3 * c) * HW;
    for (int e = tid; e < 3 * 32 * 32; e += NTHREADS) {
        const int j  = e >> 10;
        const int r  = e & 1023;
        const int ly = r >> 5;
        const int lx = r & 31;
        const int gy = ty0 - 2 + ly;
        const int gx = tx0 - 2 + lx;
        float v = 0.f;
        if ((unsigned)gy < (unsigned)H_IMG && (unsigned)gx < (unsigned)W_IMG)
            v = xb[(size_t)j * HW + gy * W_IMG + gx];
        xs[j][ly][lx] = v;
    }
    __syncthreads();

    // ---- Phase A: GEMV. Thread t<196 owns pixels (oy, ox..ox+3). ----
    float l[4][9];
#pragma unroll
    for (int px = 0; px < 4; px++)
#pragma unroll
        for (int i = 0; i < 9; i++) l[px][i] = 0.f;

    const int oy = tid / 7;            // 0..27  (valid only for tid<196)
    const int ox = (tid % 7) * 4;      // 0,4,...,24
    const int gy = ty0 + oy;
    const int gx = tx0 + ox;

    if (tid < NGROUPS) {
        const float* xq = x + (size_t)b * CIN * HW + gy * W_IMG + gx;
#pragma unroll 4
        for (int cin = 0; cin < CIN; cin++) {
            const float4 xv = *reinterpret_cast<const float4*>(xq + (size_t)cin * HW);
            const float4 f0 = *reinterpret_cast<const float4*>(&fcs_t[cin][0]);
            const float4 f1 = *reinterpret_cast<const float4*>(&fcs_t[cin][4]);
            const float  f8 = fcs_t[cin][8];
            const float w[9] = {f0.x, f0.y, f0.z, f0.w, f1.x, f1.y, f1.z, f1.w, f8};
            const float xr[4] = {xv.x, xv.y, xv.z, xv.w};
#pragma unroll
            for (int px = 0; px < 4; px++)
#pragma unroll
                for (int i = 0; i < 9; i++)
                    l[px][i] = fmaf(w[i], xr[px], l[px][i]);
        }
    }
    __syncthreads();   // GEMV done reading pool; safe to overwrite with fs

    // ---- Phase B: feat tile fs[i][fy][fx] on 30x30 (halo 1), computed once ----
    for (int e = tid; e < 9 * 30 * 30; e += NTHREADS) {
        const int i  = e / 900;
        const int r  = e - i * 900;
        const int fy = r / 30;
        const int fx = r - fy * 30;
        const int fgy = ty0 - 1 + fy;
        const int fgx = tx0 - 1 + fx;
        float v = 0.f;
        if ((unsigned)fgy < (unsigned)H_IMG && (unsigned)fgx < (unsigned)W_IMG) {
            const float* wp = &w1s[i][0];
            float a = 0.f;
#pragma unroll
            for (int j = 0; j < 3; j++)
#pragma unroll
                for (int kh = 0; kh < 3; kh++)
#pragma unroll
                    for (int kw = 0; kw < 3; kw++)
                        a = fmaf(wp[j * 9 + kh * 3 + kw],
                                 xs[j][fy + kh][fx + kw], a);
            v = fmaxf(a, 0.f);
        }
        fs[e] = v;   // fs[i*900 + fy*30 + fx]
    }
    __syncthreads();

    // ---- Phase C: softmax + depthwise + aggregation, float4 store ----
    if (tid < NGROUPS) {
        float res[4];
#pragma unroll
        for (int px = 0; px < 4; px++) {
            float mx = l[px][0];
#pragma unroll
            for (int i = 1; i < 9; i++) mx = fmaxf(mx, l[px][i]);
            float s = 0.f;
            float e9[9];
#pragma unroll
            for (int i = 0; i < 9; i++) {
                e9[i] = __expf(l[px][i] - mx);
                s += e9[i];
            }
            const float inv = 1.f / s;

            float acc = 0.f;
#pragma unroll
            for (int i = 0; i < 9; i++) {
                const float* fpi = &fs[i * 900 + oy * 30 + (ox + px)];
                float dw = 0.f;
#pragma unroll
                for (int kh = 0; kh < 3; kh++)
#pragma unroll
                    for (int kw = 0; kw < 3; kw++)
                        dw = fmaf(w2s[i][kh * 3 + kw], fpi[kh * 30 + kw], dw);
                acc = fmaf(e9[i] * inv, dw, acc);
            }
            res[px] = acc;
        }
        float* op = out + ((size_t)b * C_OUT + c) * HW + gy * W_IMG + gx;
        *reinterpret_cast<float4*>(op) = make_float4(res[0], res[1], res[2], res[3]);
    }
}

// ---------------------------------------------------------------------------
extern "C" void kernel_launch(void* const* d_in, const int* in_sizes, int n_in,
                              void* d_out, int out_size)
{
    // Bind inputs by element count (robust to metadata ordering)
    const float* x    = nullptr;
    const float* fc_w = nullptr;
    const float* w1   = nullptr;
    const float* w2   = nullptr;
    for (int i = 0; i < n_in; i++) {
        switch (in_sizes[i]) {
            case B_SZ * CIN * HW:            x    = (const float*)d_in[i]; break; // 14450688
            case C_OUT * KK * CIN:           fc_w = (const float*)d_in[i]; break; // 995328
            case KK * C_OUT * 3 * 3 * 3:     w1   = (const float*)d_in[i]; break; // 46656
            case KK * C_OUT * 3 * 3:         w2   = (const float*)d_in[i]; break; // 15552
            default: break;
        }
    }
    float* out = (float*)d_out;

    dim3 grid(2, 2, B_SZ * C_OUT);   // 2x2 spatial tiles x 1536 (b,c) pairs
    dynconv_fused_kernel<<<grid, NTHREADS>>>(x, fc_w, w1, w2, out);
}

// round 5
// speedup vs baseline: 2.3879x; 1.4498x over previous
#include <cuda_runtime.h>

// Problem dims
// x:    (8, 576, 56, 56)  fp32   14,450,688 elems
// fc_w: (1728, 576)       fp32      995,328 elems
// w1:   (9, 192, 3, 3, 3) fp32       46,656 elems
// w2:   (9, 192, 3, 3)    fp32       15,552 elems
// out:  (8, 192, 56, 56)  fp32

#define B_SZ 8
#define CIN 576
#define C_OUT 192
#define KK 9
#define H_IMG 56
#define W_IMG 56
#define HW 3136
#define M_G 1728
#define N_G 3136
#define K_G 576

// Scratch for logits: (B, 1728, 3136) fp32 = 173.4 MB
__device__ float g_logits[(size_t)B_SZ * M_G * N_G];

__device__ __forceinline__ unsigned long long pack2(float lo, float hi) {
    unsigned long long r;
    asm("mov.b64 %0, {%1, %2};" : "=l"(r) : "f"(lo), "f"(hi));
    return r;
}
__device__ __forceinline__ void unpack2(float& lo, float& hi, unsigned long long v) {
    asm("mov.b64 {%0, %1}, %2;" : "=f"(lo), "=f"(hi) : "l"(v));
}
__device__ __forceinline__ void fma2(unsigned long long& d,
                                     unsigned long long a,
                                     unsigned long long b) {
    asm("fma.rn.f32x2 %0, %1, %2, %0;" : "+l"(d) : "l"(a), "l"(b));
}

// ---------------------------------------------------------------------------
// Kernel 1: SGEMM  logits[b] = fc_w (1728x576) @ x[b] (576x3136)
// 128x128 tile, BK=8, 256 threads, 8x8 microtile computed as 8x4 f32x2 pairs.
// A staged replicated ({a,a} float2) so both FMA operands are raw LDS.128s.
// ---------------------------------------------------------------------------
__global__ __launch_bounds__(256, 2)
void gemm_logits_kernel(const float* __restrict__ A,   // fc_w (1728,576)
                        const float* __restrict__ X)   // x    (8,576,3136)
{
    const int b  = blockIdx.z;
    const float* Bp = X + (size_t)b * K_G * N_G;
    float*       Cp = g_logits + (size_t)b * M_G * N_G;
    const int m0 = blockIdx.y * 128;
    const int n0 = blockIdx.x * 128;

    __shared__ float2 As2[8][128];   // replicated {a,a}
    __shared__ float  Bs[8][128];

    const int tid = threadIdx.x;
    const int tx  = tid & 15;      // -> N
    const int ty  = tid >> 4;      // -> M

    const int arow = tid >> 1;           // 0..127
    const int acol = (tid & 1) << 2;     // 0 or 4
    const int brow = tid >> 5;           // 0..7
    const int bcol = (tid & 31) << 2;    // 0..124

    const bool aval = (m0 + arow) < M_G;
    const bool bval = (n0 + bcol) < N_G;
    const float* Aptr = A  + (size_t)(m0 + arow) * K_G + acol;
    const float* Bptr = Bp + (size_t)brow * N_G + n0 + bcol;

    unsigned long long acc[8][4];
    const unsigned long long z2 = pack2(0.f, 0.f);
#pragma unroll
    for (int i = 0; i < 8; i++)
#pragma unroll
        for (int j = 0; j < 4; j++) acc[i][j] = z2;

    for (int k0 = 0; k0 < K_G; k0 += 8) {
        float4 av = make_float4(0.f, 0.f, 0.f, 0.f);
        float4 bv = make_float4(0.f, 0.f, 0.f, 0.f);
        if (aval) av = *reinterpret_cast<const float4*>(Aptr + k0);
        if (bval) bv = *reinterpret_cast<const float4*>(Bptr + (size_t)k0 * N_G);

        As2[acol + 0][arow] = make_float2(av.x, av.x);
        As2[acol + 1][arow] = make_float2(av.y, av.y);
        As2[acol + 2][arow] = make_float2(av.z, av.z);
        As2[acol + 3][arow] = make_float2(av.w, av.w);
        *reinterpret_cast<float4*>(&Bs[brow][bcol]) = bv;
        __syncthreads();

#pragma unroll
        for (int kk = 0; kk < 8; kk++) {
            ulonglong2 a01 = *reinterpret_cast<const ulonglong2*>(&As2[kk][ty * 4]);
            ulonglong2 a23 = *reinterpret_cast<const ulonglong2*>(&As2[kk][ty * 4 + 2]);
            ulonglong2 a45 = *reinterpret_cast<const ulonglong2*>(&As2[kk][64 + ty * 4]);
            ulonglong2 a67 = *reinterpret_cast<const ulonglong2*>(&As2[kk][64 + ty * 4 + 2]);
            ulonglong2 b01 = *reinterpret_cast<const ulonglong2*>(&Bs[kk][tx * 4]);
            ulonglong2 b23 = *reinterpret_cast<const ulonglong2*>(&Bs[kk][64 + tx * 4]);
            const unsigned long long a8[8] = {a01.x, a01.y, a23.x, a23.y,
                                              a45.x, a45.y, a67.x, a67.y};
            const unsigned long long b4[4] = {b01.x, b01.y, b23.x, b23.y};
#pragma unroll
            for (int i = 0; i < 8; i++)
#pragma unroll
                for (int j = 0; j < 4; j++)
                    fma2(acc[i][j], a8[i], b4[j]);
        }
        __syncthreads();
    }

    // Epilogue
#pragma unroll
    for (int i = 0; i < 8; i++) {
        const int m = m0 + ((i < 4) ? (ty * 4 + i) : (64 + ty * 4 + (i - 4)));
        if (m >= M_G) continue;
        float* crow = Cp + (size_t)m * N_G;
        const int n1 = n0 + tx * 4;
        const int n2 = n0 + 64 + tx * 4;
        float4 v;
        if (n1 < N_G) {
            unpack2(v.x, v.y, acc[i][0]);
            unpack2(v.z, v.w, acc[i][1]);
            *reinterpret_cast<float4*>(crow + n1) = v;
        }
        if (n2 < N_G) {
            unpack2(v.x, v.y, acc[i][2]);
            unpack2(v.z, v.w, acc[i][3]);
            *reinterpret_cast<float4*>(crow + n2) = v;
        }
    }
}

// ---------------------------------------------------------------------------
// Kernel 2: fused grouped-conv1+ReLU + softmax(g_logits) + depthwise-conv2
//           + weighted aggregation.  One block = (b, c, 28x28 tile).
// ---------------------------------------------------------------------------
#define NT2 224
#define NGROUPS 196

__global__ __launch_bounds__(NT2)
void fused_tail_kernel(const float* __restrict__ x,
                       const float* __restrict__ w1,
                       const float* __restrict__ w2,
                       float* __restrict__ out)
{
    __shared__ float xs[3][32][32];     // x channels 3c..3c+2, tile + halo 2
    __shared__ float fs[9 * 30 * 30];   // feat tile, halo 1
    __shared__ float w1s[9][27];
    __shared__ float w2s[9][9];

    const int bc  = blockIdx.z;
    const int b   = bc / C_OUT;
    const int c   = bc % C_OUT;
    const int ty0 = blockIdx.y * 28;
    const int tx0 = blockIdx.x * 28;
    const int tid = threadIdx.x;

    // weights via strided loops (ALL elements covered regardless of blockDim)
    for (int e = tid; e < 243; e += NT2)
        w1s[e / 27][e % 27] = w1[(size_t)(e / 27) * (C_OUT * 27) + c * 27 + (e % 27)];
    for (int e = tid; e < 81; e += NT2)
        w2s[e / 9][e % 9] = w2[(size_t)(e / 9) * (C_OUT * 9) + c * 9 + (e % 9)];

    // x tile (3 ch, 32x32, halo 2, zero outside)
    const float* xb = x + ((size_t)b * CIN + 3 * c) * HW;
    for (int e = tid; e < 3 * 32 * 32; e += NT2) {
        const int j  = e >> 10;
        const int r  = e & 1023;
        const int ly = r >> 5;
        const int lx = r & 31;
        const int gy = ty0 - 2 + ly;
        const int gx = tx0 - 2 + lx;
        float v = 0.f;
        if ((unsigned)gy < (unsigned)H_IMG && (unsigned)gx < (unsigned)W_IMG)
            v = xb[(size_t)j * HW + gy * W_IMG + gx];
        xs[j][ly][lx] = v;
    }
    __syncthreads();

    // feat tile fs[i][fy][fx] on 30x30 (halo 1), computed once
    for (int e = tid; e < 9 * 30 * 30; e += NT2) {
        const int i  = e / 900;
        const int r  = e - i * 900;
        const int fy = r / 30;
        const int fx = r - fy * 30;
        const int fgy = ty0 - 1 + fy;
        const int fgx = tx0 - 1 + fx;
        float v = 0.f;
        if ((unsigned)fgy < (unsigned)H_IMG && (unsigned)fgx < (unsigned)W_IMG) {
            const float* wp = &w1s[i][0];
            float a = 0.f;
#pragma unroll
            for (int j = 0; j < 3; j++)
#pragma unroll
                for (int kh = 0; kh < 3; kh++)
#pragma unroll
                    for (int kw = 0; kw < 3; kw++)
                        a = fmaf(wp[j * 9 + kh * 3 + kw],
                                 xs[j][fy + kh][fx + kw], a);
            v = fmaxf(a, 0.f);
        }
        fs[e] = v;
    }
    __syncthreads();

    // per 4-pixel group: read 9 logits (float4), softmax, depthwise, aggregate
    if (tid < NGROUPS) {
        const int oy = tid / 7;
        const int ox = (tid % 7) * 4;
        const int gy = ty0 + oy;
        const int gx = tx0 + ox;
        const int p  = gy * W_IMG + gx;

        const float* lbase = g_logits + ((size_t)b * M_G + (size_t)c * KK) * N_G + p;
        float l[4][9];
#pragma unroll
        for (int i = 0; i < 9; i++) {
            const float4 lv = *reinterpret_cast<const float4*>(lbase + (size_t)i * N_G);
            l[0][i] = lv.x; l[1][i] = lv.y; l[2][i] = lv.z; l[3][i] = lv.w;
        }

        float res[4];
#pragma unroll
        for (int px = 0; px < 4; px++) {
            float mx = l[px][0];
#pragma unroll
            for (int i = 1; i < 9; i++) mx = fmaxf(mx, l[px][i]);
            float s = 0.f;
            float e9[9];
#pragma unroll
            for (int i = 0; i < 9; i++) {
                e9[i] = __expf(l[px][i] - mx);
                s += e9[i];
            }
            const float inv = 1.f / s;

            float acc = 0.f;
#pragma unroll
            for (int i = 0; i < 9; i++) {
                const float* fpi = &fs[i * 900 + oy * 30 + (ox + px)];
                float dw = 0.f;
#pragma unroll
                for (int kh = 0; kh < 3; kh++)
#pragma unroll
                    for (int kw = 0; kw < 3; kw++)
                        dw = fmaf(w2s[i][kh * 3 + kw], fpi[kh * 30 + kw], dw);
                acc = fmaf(e9[i] * inv, dw, acc);
            }
            res[px] = acc;
        }
        float* op = out + ((size_t)b * C_OUT + c) * HW + p;
        *reinterpret_cast<float4*>(op) = make_float4(res[0], res[1], res[2], res[3]);
    }
}

// ---------------------------------------------------------------------------
extern "C" void kernel_launch(void* const* d_in, const int* in_sizes, int n_in,
                              void* d_out, int out_size)
{
    // Bind inputs by element count (robust to metadata ordering)
    const float* x    = nullptr;
    const float* fc_w = nullptr;
    const float* w1   = nullptr;
    const float* w2   = nullptr;
    for (int i = 0; i < n_in; i++) {
        switch (in_sizes[i]) {
            case B_SZ * CIN * HW:            x    = (const float*)d_in[i]; break; // 14450688
            case C_OUT * KK * CIN:           fc_w = (const float*)d_in[i]; break; // 995328
            case KK * C_OUT * 3 * 3 * 3:     w1   = (const float*)d_in[i]; break; // 46656
            case KK * C_OUT * 3 * 3:         w2   = (const float*)d_in[i]; break; // 15552
            default: break;
        }
    }
    float* out = (float*)d_out;

    // K1: GEMM -> g_logits
    dim3 g1((N_G + 127) / 128, (M_G + 127) / 128, B_SZ);  // 25 x 14 x 8
    gemm_logits_kernel<<<g1, 256>>>(fc_w, x);

    // K2: fused tail
    dim3 g2(2, 2, B_SZ * C_OUT);                           // 2 x 2 x 1536
    fused_tail_kernel<<<g2, NT2>>>(x, w1, w2, out);
}

// round 6
// speedup vs baseline: 3.0834x; 1.2913x over previous
#include <cuda_runtime.h>

// Problem dims
// x:    (8, 576, 56, 56)  fp32   14,450,688 elems
// fc_w: (1728, 576)       fp32      995,328 elems
// w1:   (9, 192, 3, 3, 3) fp32       46,656 elems
// w2:   (9, 192, 3, 3)    fp32       15,552 elems
// out:  (8, 192, 56, 56)  fp32

#define B_SZ 8
#define CIN 576
#define C_OUT 192
#define KK 9
#define H_IMG 56
#define W_IMG 56
#define HW 3136
#define M_G 1728
#define N_G 3136
#define K_G 576

// Scratch for logits: (B, 1728, 3136) fp32 = 173.4 MB
__device__ float g_logits[(size_t)B_SZ * M_G * N_G];

__device__ __forceinline__ unsigned long long pack_dup(float a) {
    unsigned long long r;
    asm("mov.b64 %0, {%1, %1};" : "=l"(r) : "f"(a));
    return r;
}
__device__ __forceinline__ void unpack2(float& lo, float& hi, unsigned long long v) {
    asm("mov.b64 {%0, %1}, %2;" : "=f"(lo), "=f"(hi) : "l"(v));
}
__device__ __forceinline__ void fma2(unsigned long long& d,
                                     unsigned long long a,
                                     unsigned long long b) {
    asm("fma.rn.f32x2 %0, %1, %2, %0;" : "+l"(d) : "l"(a), "l"(b));
}

// ---------------------------------------------------------------------------
// Kernel 1: SGEMM  logits[b] = fc_w (1728x576) @ x[b] (576x3136)
// 128x128 tile, BK=8, 256 threads, 8x8 microtile as 8x4 f32x2 (pairs over N).
// A smem scalar (no replication): 64B LDS/thread-kk; broadcast operand built
// with mov.b64 {a,a} on the ALU pipe.  fma.rn.f32x2 on the FMA pipe.
// ---------------------------------------------------------------------------
__global__ __launch_bounds__(256, 2)
void gemm_logits_kernel(const float* __restrict__ A,   // fc_w (1728,576)
                        const float* __restrict__ X)   // x    (8,576,3136)
{
    const int b  = blockIdx.z;
    const float* Bp = X + (size_t)b * K_G * N_G;
    float*       Cp = g_logits + (size_t)b * M_G * N_G;
    const int m0 = blockIdx.y * 128;
    const int n0 = blockIdx.x * 128;

    __shared__ float As[8][128];
    __shared__ float Bs[8][128];

    const int tid = threadIdx.x;
    const int tx  = tid & 15;      // -> N
    const int ty  = tid >> 4;      // -> M

    const int arow = tid >> 1;           // 0..127
    const int acol = (tid & 1) << 2;     // 0 or 4
    const int brow = tid >> 5;           // 0..7
    const int bcol = (tid & 31) << 2;    // 0..124

    const bool aval = (m0 + arow) < M_G;
    const bool bval = (n0 + bcol) < N_G;
    const float* Aptr = A  + (size_t)(m0 + arow) * K_G + acol;
    const float* Bptr = Bp + (size_t)brow * N_G + n0 + bcol;

    unsigned long long acc[8][4];
#pragma unroll
    for (int i = 0; i < 8; i++)
#pragma unroll
        for (int j = 0; j < 4; j++) acc[i][j] = pack_dup(0.f);

    for (int k0 = 0; k0 < K_G; k0 += 8) {
        float4 av = make_float4(0.f, 0.f, 0.f, 0.f);
        float4 bv = make_float4(0.f, 0.f, 0.f, 0.f);
        if (aval) av = *reinterpret_cast<const float4*>(Aptr + k0);
        if (bval) bv = *reinterpret_cast<const float4*>(Bptr + (size_t)k0 * N_G);

        As[acol + 0][arow] = av.x;
        As[acol + 1][arow] = av.y;
        As[acol + 2][arow] = av.z;
        As[acol + 3][arow] = av.w;
        *reinterpret_cast<float4*>(&Bs[brow][bcol]) = bv;
        __syncthreads();

#pragma unroll
        for (int kk = 0; kk < 8; kk++) {
            const float4 a0 = *reinterpret_cast<const float4*>(&As[kk][ty * 4]);
            const float4 a1 = *reinterpret_cast<const float4*>(&As[kk][64 + ty * 4]);
            const ulonglong2 b01 = *reinterpret_cast<const ulonglong2*>(&Bs[kk][tx * 4]);
            const ulonglong2 b23 = *reinterpret_cast<const ulonglong2*>(&Bs[kk][64 + tx * 4]);
            const unsigned long long a8[8] = {
                pack_dup(a0.x), pack_dup(a0.y), pack_dup(a0.z), pack_dup(a0.w),
                pack_dup(a1.x), pack_dup(a1.y), pack_dup(a1.z), pack_dup(a1.w)};
            const unsigned long long b4[4] = {b01.x, b01.y, b23.x, b23.y};
#pragma unroll
            for (int i = 0; i < 8; i++)
#pragma unroll
                for (int j = 0; j < 4; j++)
                    fma2(acc[i][j], a8[i], b4[j]);
        }
        __syncthreads();
    }

    // Epilogue
#pragma unroll
    for (int i = 0; i < 8; i++) {
        const int m = m0 + ((i < 4) ? (ty * 4 + i) : (64 + ty * 4 + (i - 4)));
        if (m >= M_G) continue;
        float* crow = Cp + (size_t)m * N_G;
        const int n1 = n0 + tx * 4;
        const int n2 = n0 + 64 + tx * 4;
        float4 v;
        if (n1 < N_G) {
            unpack2(v.x, v.y, acc[i][0]);
            unpack2(v.z, v.w, acc[i][1]);
            *reinterpret_cast<float4*>(crow + n1) = v;
        }
        if (n2 < N_G) {
            unpack2(v.x, v.y, acc[i][2]);
            unpack2(v.z, v.w, acc[i][3]);
            *reinterpret_cast<float4*>(crow + n2) = v;
        }
    }
}

// ---------------------------------------------------------------------------
// Kernel 2: fused grouped-conv1+ReLU + softmax(g_logits) + depthwise-conv2
//           + weighted aggregation.  One block = (b, c, 28x28 tile).
// 256 threads, one pixel per thread-iteration (low register pressure).
// ---------------------------------------------------------------------------
#define NT2 256

__global__ __launch_bounds__(NT2)
void fused_tail_kernel(const float* __restrict__ x,
                       const float* __restrict__ w1,
                       const float* __restrict__ w2,
                       float* __restrict__ out)
{
    __shared__ float xs[3][32][32];     // x channels 3c..3c+2, tile + halo 2
    __shared__ float fs[9 * 30 * 30];   // feat tile, halo 1
    __shared__ float w1s[9][27];
    __shared__ float w2s[9][9];

    const int bc  = blockIdx.z;
    const int b   = bc / C_OUT;
    const int c   = bc % C_OUT;
    const int ty0 = blockIdx.y * 28;
    const int tx0 = blockIdx.x * 28;
    const int tid = threadIdx.x;

    // weights via strided loops (all elements covered regardless of blockDim)
    for (int e = tid; e < 243; e += NT2)
        w1s[e / 27][e % 27] = w1[(size_t)(e / 27) * (C_OUT * 27) + c * 27 + (e % 27)];
    for (int e = tid; e < 81; e += NT2)
        w2s[e / 9][e % 9] = w2[(size_t)(e / 9) * (C_OUT * 9) + c * 9 + (e % 9)];

    // x tile (3 ch, 32x32, halo 2, zero outside)
    const float* xb = x + ((size_t)b * CIN + 3 * c) * HW;
    for (int e = tid; e < 3 * 32 * 32; e += NT2) {
        const int j  = e >> 10;
        const int r  = e & 1023;
        const int ly = r >> 5;
        const int lx = r & 31;
        const int gy = ty0 - 2 + ly;
        const int gx = tx0 - 2 + lx;
        float v = 0.f;
        if ((unsigned)gy < (unsigned)H_IMG && (unsigned)gx < (unsigned)W_IMG)
            v = xb[(size_t)j * HW + gy * W_IMG + gx];
        xs[j][ly][lx] = v;
    }
    __syncthreads();

    // feat tile fs[i][fy][fx] on 30x30 (halo 1), computed once
    for (int e = tid; e < 9 * 30 * 30; e += NT2) {
        const int i  = e / 900;
        const int r  = e - i * 900;
        const int fy = r / 30;
        const int fx = r - fy * 30;
        const int fgy = ty0 - 1 + fy;
        const int fgx = tx0 - 1 + fx;
        float v = 0.f;
        if ((unsigned)fgy < (unsigned)H_IMG && (unsigned)fgx < (unsigned)W_IMG) {
            const float* wp = &w1s[i][0];
            float a = 0.f;
#pragma unroll
            for (int j = 0; j < 3; j++)
#pragma unroll
                for (int kh = 0; kh < 3; kh++)
#pragma unroll
                    for (int kw = 0; kw < 3; kw++)
                        a = fmaf(wp[j * 9 + kh * 3 + kw],
                                 xs[j][fy + kh][fx + kw], a);
            v = fmaxf(a, 0.f);
        }
        fs[e] = v;
    }
    __syncthreads();

    // per pixel: read 9 logits, softmax, depthwise conv2, aggregate
    const float* lblk = g_logits + ((size_t)b * M_G + (size_t)c * KK) * N_G;
    float* ob = out + ((size_t)b * C_OUT + c) * HW;
    for (int e = tid; e < 28 * 28; e += NT2) {
        const int oy = e / 28;
        const int ox = e - oy * 28;
        const int p  = (ty0 + oy) * W_IMG + (tx0 + ox);

        float l[9];
#pragma unroll
        for (int i = 0; i < 9; i++)
            l[i] = lblk[(size_t)i * N_G + p];

        float mx = l[0];
#pragma unroll
        for (int i = 1; i < 9; i++) mx = fmaxf(mx, l[i]);
        float s = 0.f;
#pragma unroll
        for (int i = 0; i < 9; i++) {
            l[i] = __expf(l[i] - mx);
            s += l[i];
        }
        const float inv = 1.f / s;

        float acc = 0.f;
#pragma unroll
        for (int i = 0; i < 9; i++) {
            const float* fpi = &fs[i * 900 + oy * 30 + ox];
            float dw = 0.f;
#pragma unroll
            for (int kh = 0; kh < 3; kh++)
#pragma unroll
                for (int kw = 0; kw < 3; kw++)
                    dw = fmaf(w2s[i][kh * 3 + kw], fpi[kh * 30 + kw], dw);
            acc = fmaf(l[i] * inv, dw, acc);
        }
        ob[p] = acc;
    }
}

// ---------------------------------------------------------------------------
extern "C" void kernel_launch(void* const* d_in, const int* in_sizes, int n_in,
                              void* d_out, int out_size)
{
    // Bind inputs by element count (robust to metadata ordering)
    const float* x    = nullptr;
    const float* fc_w = nullptr;
    const float* w1   = nullptr;
    const float* w2   = nullptr;
    for (int i = 0; i < n_in; i++) {
        switch (in_sizes[i]) {
            case B_SZ * CIN * HW:            x    = (const float*)d_in[i]; break; // 14450688
            case C_OUT * KK * CIN:           fc_w = (const float*)d_in[i]; break; // 995328
            case KK * C_OUT * 3 * 3 * 3:     w1   = (const float*)d_in[i]; break; // 46656
            case KK * C_OUT * 3 * 3:         w2   = (const float*)d_in[i]; break; // 15552
            default: break;
        }
    }
    float* out = (float*)d_out;

    // K1: GEMM -> g_logits
    dim3 g1((N_G + 127) / 128, (M_G + 127) / 128, B_SZ);  // 25 x 14 x 8
    gemm_logits_kernel<<<g1, 256>>>(fc_w, x);

    // K2: fused tail
    dim3 g2(2, 2, B_SZ * C_OUT);                           // 2 x 2 x 1536
    fused_tail_kernel<<<g2, NT2>>>(x, w1, w2, out);
}

// round 10
// speedup vs baseline: 4.1162x; 1.3349x over previous
#include <cuda_runtime.h>
#include <cuda_bf16.h>
#include <cstdint>

// Problem dims
#define B_SZ 8
#define CIN 576
#define C_OUT 192
#define KK 9
#define H_IMG 56
#define W_IMG 56
#define HW 3136
#define M_G 1728
#define N_G 3136
#define K_G 576
#define KP 1728              // K' = 3*576 (hi*hi + hi*lo + lo*hi)

// Scratch (device globals: referenced ONLY from device code!)
__device__ float g_logits[(size_t)B_SZ * M_G * N_G];                  // 173 MB
__device__ __nv_bfloat16 g_At[(size_t)M_G * KP];                      // 6 MB
__device__ __nv_bfloat16 g_Xt[(size_t)B_SZ * N_G * KP];               // 87 MB

// ---------------------------------------------------------------------------
// Pack A: fc_w (1728x576) fp32 -> At (1728x1728) bf16 = [hi | hi | lo]
// ---------------------------------------------------------------------------
__global__ void pack_A_kernel(const float* __restrict__ fc_w) {
    const int e = blockIdx.x * 256 + threadIdx.x;
    if (e >= M_G * K_G) return;
    const int m = e / K_G;
    const int k = e - m * K_G;
    const float a = fc_w[e];
    const __nv_bfloat16 hi = __float2bfloat16(a);
    const __nv_bfloat16 lo = __float2bfloat16(a - __bfloat162float(hi));
    __nv_bfloat16* r = g_At + (size_t)m * KP;
    r[k]        = hi;
    r[576 + k]  = hi;
    r[1152 + k] = lo;
}

// ---------------------------------------------------------------------------
// Pack X: x (8,576,3136) fp32 -> Xt (8,3136,1728) bf16 = [hi ; lo ; hi]
// ---------------------------------------------------------------------------
__global__ __launch_bounds__(256)
void pack_X_kernel(const float* __restrict__ x) {
    __shared__ float t[32][33];
    const int bz = blockIdx.z;
    const int k0 = blockIdx.y * 32;
    const int n0 = blockIdx.x * 32;
    const int tx = threadIdx.x & 31;
    const int ty = threadIdx.x >> 5;   // 0..7

    const float* xb = x + (size_t)bz * CIN * HW;
#pragma unroll
    for (int i = 0; i < 4; i++) {
        const int k = k0 + ty + i * 8;
        t[ty + i * 8][tx] = xb[(size_t)k * HW + n0 + tx];
    }
    __syncthreads();

    __nv_bfloat16* Xb = g_Xt + (size_t)bz * N_G * KP;
#pragma unroll
    for (int i = 0; i < 4; i++) {
        const int n = n0 + ty + i * 8;
        const float a = t[tx][ty + i * 8];
        const __nv_bfloat16 hi = __float2bfloat16(a);
        const __nv_bfloat16 lo = __float2bfloat16(a - __bfloat162float(hi));
        __nv_bfloat16* r = Xb + (size_t)n * KP;
        r[k0 + tx]        = hi;
        r[576 + k0 + tx]  = lo;
        r[1152 + k0 + tx] = hi;
    }
}

// ---------------------------------------------------------------------------
// HMMA GEMM: logits[b] = At (1728x1728) @ Xt[b]^T, bf16 mma.sync m16n8k16.
// Block 128x128, K-stage 64. Smem rows padded to 72 bf16 (144B): fragment
// LDS conflict-free. Guarded LDG float4 + STS + register prefetch,
// double buffered. 8 warps = 4(m) x 2(n); warp tile 32x64.
// Reads g_At/g_Xt as device globals (NOT host-passed args).
// ---------------------------------------------------------------------------
#define KS 64
#define NST 27                         // 1728/64
#define RSTRIDE 72                     // bf16 elems per smem row (64 + 8 pad)
#define TILE_ELEMS (128 * RSTRIDE)
#define DSMEM_ELEMS (4 * TILE_ELEMS)   // A0,B0,A1,B1
#define DSMEM_BYTES (DSMEM_ELEMS * 2 + 256)

__global__ __launch_bounds__(256)
void gemm_mma_kernel()
{
    extern __shared__ __align__(16) __nv_bfloat16 smp[];

    const int tid  = threadIdx.x;
    const int lane = tid & 31;
    const int wid  = tid >> 5;
    const int wm   = wid >> 1;        // 0..3
    const int wn   = wid & 1;         // 0..1

    const int b  = blockIdx.z;
    const int m0 = blockIdx.y * 128;
    const int n0 = blockIdx.x * 128;
    const __nv_bfloat16* At = g_At;
    const __nv_bfloat16* Xb = g_Xt + (size_t)b * N_G * KP;
    float* Cp = g_logits + (size_t)b * M_G * N_G;

    __nv_bfloat16* Abuf[2] = {smp,              smp + 2 * TILE_ELEMS};
    __nv_bfloat16* Bbuf[2] = {smp + TILE_ELEMS, smp + 3 * TILE_ELEMS};

    float acc[2][8][4];
#pragma unroll
    for (int mt = 0; mt < 2; mt++)
#pragma unroll
        for (int nt = 0; nt < 8; nt++)
#pragma unroll
            for (int r = 0; r < 4; r++) acc[mt][nt][r] = 0.f;

    uint4 ra[4], rb[4];
    const uint4 zq = make_uint4(0u, 0u, 0u, 0u);
    int rowc[4], kcc[4];
#pragma unroll
    for (int i = 0; i < 4; i++) {
        const int ch = tid + i * 256;
        rowc[i] = ch >> 3;
        kcc[i]  = ch & 7;
    }

    auto LDG_STAGE = [&](int s) {
        const int k0 = s * KS;
#pragma unroll
        for (int i = 0; i < 4; i++) {
            const int m = m0 + rowc[i];
            ra[i] = (m < M_G)
                ? *reinterpret_cast<const uint4*>(At + (size_t)m * KP + k0 + kcc[i] * 8)
                : zq;
            const int n = n0 + rowc[i];
            rb[i] = (n < N_G)
                ? *reinterpret_cast<const uint4*>(Xb + (size_t)n * KP + k0 + kcc[i] * 8)
                : zq;
        }
    };
    auto STS_STAGE = [&](int buf) {
#pragma unroll
        for (int i = 0; i < 4; i++) {
            const int off = rowc[i] * RSTRIDE + kcc[i] * 8;
            *reinterpret_cast<uint4*>(Abuf[buf] + off) = ra[i];
            *reinterpret_cast<uint4*>(Bbuf[buf] + off) = rb[i];
        }
    };

    auto COMPUTE = [&](int s) {
        const int buf = s & 1;
        const __nv_bfloat16* A = Abuf[buf];
        const __nv_bfloat16* B = Bbuf[buf];
        const int lq = lane >> 2;           // 0..7
        const int lr = (lane & 3) * 2;      // 0,2,4,6
#pragma unroll
        for (int kk = 0; kk < 4; kk++) {
            const int k0 = kk * 16;

            uint32_t a[2][4];
#pragma unroll
            for (int mt = 0; mt < 2; mt++) {
                const int base = (wm * 32 + mt * 16 + lq) * RSTRIDE + k0 + lr;
                a[mt][0] = *reinterpret_cast<const uint32_t*>(A + base);
                a[mt][1] = *reinterpret_cast<const uint32_t*>(A + base + 8 * RSTRIDE);
                a[mt][2] = *reinterpret_cast<const uint32_t*>(A + base + 8);
                a[mt][3] = *reinterpret_cast<const uint32_t*>(A + base + 8 * RSTRIDE + 8);
            }
            uint32_t bf[8][2];
#pragma unroll
            for (int nt = 0; nt < 8; nt++) {
                const int base = (wn * 64 + nt * 8 + lq) * RSTRIDE + k0 + lr;
                bf[nt][0] = *reinterpret_cast<const uint32_t*>(B + base);
                bf[nt][1] = *reinterpret_cast<const uint32_t*>(B + base + 8);
            }

#pragma unroll
            for (int mt = 0; mt < 2; mt++)
#pragma unroll
                for (int nt = 0; nt < 8; nt++)
                    asm volatile(
                        "mma.sync.aligned.m16n8k16.row.col.f32.bf16.bf16.f32 "
                        "{%0,%1,%2,%3}, {%4,%5,%6,%7}, {%8,%9}, {%0,%1,%2,%3};"
                        : "+f"(acc[mt][nt][0]), "+f"(acc[mt][nt][1]),
                          "+f"(acc[mt][nt][2]), "+f"(acc[mt][nt][3])
                        : "r"(a[mt][0]), "r"(a[mt][1]), "r"(a[mt][2]), "r"(a[mt][3]),
                          "r"(bf[nt][0]), "r"(bf[nt][1]));
        }
    };

    LDG_STAGE(0);
    STS_STAGE(0);
    LDG_STAGE(1);
    __syncthreads();
    for (int s = 0; s < NST; s++) {
        COMPUTE(s);
        if (s + 1 < NST) {
            STS_STAGE((s + 1) & 1);
            if (s + 2 < NST) LDG_STAGE(s + 2);
            __syncthreads();
        }
    }

    // Epilogue: D fragment -> g_logits
    const int rbase = lane >> 2;
    const int cbase = (lane & 3) * 2;
#pragma unroll
    for (int mt = 0; mt < 2; mt++) {
#pragma unroll
        for (int nt = 0; nt < 8; nt++) {
            const int row = m0 + wm * 32 + mt * 16 + rbase;
            const int col = n0 + wn * 64 + nt * 8 + cbase;
            if (col < N_G) {
                if (row < M_G)
                    *reinterpret_cast<float2*>(Cp + (size_t)row * N_G + col) =
                        make_float2(acc[mt][nt][0], acc[mt][nt][1]);
                if (row + 8 < M_G)
                    *reinterpret_cast<float2*>(Cp + (size_t)(row + 8) * N_G + col) =
                        make_float2(acc[mt][nt][2], acc[mt][nt][3]);
            }
        }
    }
}

// ---------------------------------------------------------------------------
// Kernel 2: fused tail (R6-verified)
// ---------------------------------------------------------------------------
#define NT2 256

__global__ __launch_bounds__(NT2, 3)
void fused_tail_kernel(const float* __restrict__ x,
                       const float* __restrict__ w1,
                       const float* __restrict__ w2,
                       float* __restrict__ out)
{
    __shared__ float xs[3][32][32];
    __shared__ float fs[9 * 30 * 30];
    __shared__ float w1s[9][27];
    __shared__ float w2s[9][9];

    const int bc  = blockIdx.z;
    const int b   = bc / C_OUT;
    const int c   = bc % C_OUT;
    const int ty0 = blockIdx.y * 28;
    const int tx0 = blockIdx.x * 28;
    const int tid = threadIdx.x;

    for (int e = tid; e < 243; e += NT2)
        w1s[e / 27][e % 27] = w1[(size_t)(e / 27) * (C_OUT * 27) + c * 27 + (e % 27)];
    for (int e = tid; e < 81; e += NT2)
        w2s[e / 9][e % 9] = w2[(size_t)(e / 9) * (C_OUT * 9) + c * 9 + (e % 9)];

    const float* xb = x + ((size_t)b * CIN + 3 * c) * HW;
    for (int e = tid; e < 3 * 32 * 32; e += NT2) {
        const int j  = e >> 10;
        const int r  = e & 1023;
        const int ly = r >> 5;
        const int lx = r & 31;
        const int gy = ty0 - 2 + ly;
        const int gx = tx0 - 2 + lx;
        float v = 0.f;
        if ((unsigned)gy < (unsigned)H_IMG && (unsigned)gx < (unsigned)W_IMG)
            v = xb[(size_t)j * HW + gy * W_IMG + gx];
        xs[j][ly][lx] = v;
    }
    __syncthreads();

    for (int e = tid; e < 9 * 30 * 30; e += NT2) {
        const int i  = e / 900;
        const int r  = e - i * 900;
        const int fy = r / 30;
        const int fx = r - fy * 30;
        const int fgy = ty0 - 1 + fy;
        const int fgx = tx0 - 1 + fx;
        float v = 0.f;
        if ((unsigned)fgy < (unsigned)H_IMG && (unsigned)fgx < (unsigned)W_IMG) {
            const float* wp = &w1s[i][0];
            float a = 0.f;
#pragma unroll
            for (int j = 0; j < 3; j++)
#pragma unroll
                for (int kh = 0; kh < 3; kh++)
#pragma unroll
                    for (int kw = 0; kw < 3; kw++)
                        a = fmaf(wp[j * 9 + kh * 3 + kw],
                                 xs[j][fy + kh][fx + kw], a);
            v = fmaxf(a, 0.f);
        }
        fs[e] = v;
    }
    __syncthreads();

    const float* lblk = g_logits + ((size_t)b * M_G + (size_t)c * KK) * N_G;
    float* ob = out + ((size_t)b * C_OUT + c) * HW;
    for (int e = tid; e < 28 * 28; e += NT2) {
        const int oy = e / 28;
        const int ox = e - oy * 28;
        const int p  = (ty0 + oy) * W_IMG + (tx0 + ox);

        float l[9];
#pragma unroll
        for (int i = 0; i < 9; i++)
            l[i] = lblk[(size_t)i * N_G + p];

        float mx = l[0];
#pragma unroll
        for (int i = 1; i < 9; i++) mx = fmaxf(mx, l[i]);
        float s = 0.f;
#pragma unroll
        for (int i = 0; i < 9; i++) {
            l[i] = __expf(l[i] - mx);
            s += l[i];
        }
        const float inv = 1.f / s;

        float acc = 0.f;
#pragma unroll
        for (int i = 0; i < 9; i++) {
            const float* fpi = &fs[i * 900 + oy * 30 + ox];
            float dw = 0.f;
#pragma unroll
            for (int kh = 0; kh < 3; kh++)
#pragma unroll
                for (int kw = 0; kw < 3; kw++)
                    dw = fmaf(w2s[i][kh * 3 + kw], fpi[kh * 30 + kw], dw);
            acc = fmaf(l[i] * inv, dw, acc);
        }
        ob[p] = acc;
    }
}

// ---------------------------------------------------------------------------
extern "C" void kernel_launch(void* const* d_in, const int* in_sizes, int n_in,
                              void* d_out, int out_size)
{
    const float* x    = nullptr;
    const float* fc_w = nullptr;
    const float* w1   = nullptr;
    const float* w2   = nullptr;
    for (int i = 0; i < n_in; i++) {
        switch (in_sizes[i]) {
            case B_SZ * CIN * HW:        x    = (const float*)d_in[i]; break;
            case C_OUT * KK * CIN:       fc_w = (const float*)d_in[i]; break;
            case KK * C_OUT * 3 * 3 * 3: w1   = (const float*)d_in[i]; break;
            case KK * C_OUT * 3 * 3:     w2   = (const float*)d_in[i]; break;
            default: break;
        }
    }
    float* out = (float*)d_out;

    cudaFuncSetAttribute(gemm_mma_kernel,
                         cudaFuncAttributeMaxDynamicSharedMemorySize,
                         DSMEM_BYTES);

    // Pack (hi/lo split)
    pack_A_kernel<<<(M_G * K_G + 255) / 256, 256>>>(fc_w);
    dim3 gx(N_G / 32, K_G / 32, B_SZ);          // 98 x 18 x 8
    pack_X_kernel<<<gx, 256>>>(x);

    // HMMA GEMM -> g_logits (reads g_At/g_Xt as device globals)
    dim3 gg((N_G + 127) / 128, (M_G + 127) / 128, B_SZ);   // 25 x 14 x 8
    gemm_mma_kernel<<<gg, 256, DSMEM_BYTES>>>();

    // fused tail
    dim3 g2(2, 2, B_SZ * C_OUT);
    fused_tail_kernel<<<g2, NT2>>>(x, w1, w2, out);
}

// round 11
// speedup vs baseline: 4.1310x; 1.0036x over previous
#include <cuda_runtime.h>
#include <cuda_bf16.h>
#include <cstdint>

// Problem dims
#define B_SZ 8
#define CIN 576
#define C_OUT 192
#define KK 9
#define H_IMG 56
#define W_IMG 56
#define HW 3136
#define M_G 1728
#define N_G 3136
#define K_G 576
#define KP 1728              // K' = 3*576 (hi*hi + hi*lo + lo*hi)

// Scratch (device globals: referenced ONLY from device code!)
__device__ float g_logits[(size_t)B_SZ * M_G * N_G];                  // 173 MB
__device__ __nv_bfloat16 g_At[(size_t)M_G * KP];                      // 6 MB
__device__ __nv_bfloat16 g_Xt[(size_t)B_SZ * N_G * KP];               // 87 MB

__device__ __forceinline__ uint32_t smem_u32(const void* p) {
    uint32_t a;
    asm("{ .reg .u64 t; cvta.to.shared.u64 t, %1; cvt.u32.u64 %0, t; }"
        : "=r"(a) : "l"(p));
    return a;
}

// ---------------------------------------------------------------------------
// Pack A: fc_w (1728x576) fp32 -> At (1728x1728) bf16 = [hi | hi | lo]
// ---------------------------------------------------------------------------
__global__ void pack_A_kernel(const float* __restrict__ fc_w) {
    const int e = blockIdx.x * 256 + threadIdx.x;
    if (e >= M_G * K_G) return;
    const int m = e / K_G;
    const int k = e - m * K_G;
    const float a = fc_w[e];
    const __nv_bfloat16 hi = __float2bfloat16(a);
    const __nv_bfloat16 lo = __float2bfloat16(a - __bfloat162float(hi));
    __nv_bfloat16* r = g_At + (size_t)m * KP;
    r[k]        = hi;
    r[576 + k]  = hi;
    r[1152 + k] = lo;
}

// ---------------------------------------------------------------------------
// Pack X: x (8,576,3136) fp32 -> Xt (8,3136,1728) bf16 = [hi ; lo ; hi]
// ---------------------------------------------------------------------------
__global__ __launch_bounds__(256)
void pack_X_kernel(const float* __restrict__ x) {
    __shared__ float t[32][33];
    const int bz = blockIdx.z;
    const int k0 = blockIdx.y * 32;
    const int n0 = blockIdx.x * 32;
    const int tx = threadIdx.x & 31;
    const int ty = threadIdx.x >> 5;   // 0..7

    const float* xb = x + (size_t)bz * CIN * HW;
#pragma unroll
    for (int i = 0; i < 4; i++) {
        const int k = k0 + ty + i * 8;
        t[ty + i * 8][tx] = xb[(size_t)k * HW + n0 + tx];
    }
    __syncthreads();

    __nv_bfloat16* Xb = g_Xt + (size_t)bz * N_G * KP;
#pragma unroll
    for (int i = 0; i < 4; i++) {
        const int n = n0 + ty + i * 8;
        const float a = t[tx][ty + i * 8];
        const __nv_bfloat16 hi = __float2bfloat16(a);
        const __nv_bfloat16 lo = __float2bfloat16(a - __bfloat162float(hi));
        __nv_bfloat16* r = Xb + (size_t)n * KP;
        r[k0 + tx]        = hi;
        r[576 + k0 + tx]  = lo;
        r[1152 + k0 + tx] = hi;
    }
}

// ---------------------------------------------------------------------------
// HMMA GEMM with ldmatrix fragment loads (mapping identical to R10-verified
// direct LDS; padded 144B row stride is conflict-free for ldmatrix phases).
// ---------------------------------------------------------------------------
#define KS 64
#define NST 27                         // 1728/64
#define RSTRIDE 72                     // bf16 per smem row (64 + 8 pad = 144B)
#define TILE_ELEMS (128 * RSTRIDE)
#define DSMEM_ELEMS (4 * TILE_ELEMS)   // A0,B0,A1,B1
#define DSMEM_BYTES (DSMEM_ELEMS * 2 + 256)

__global__ __launch_bounds__(256)
void gemm_mma_kernel()
{
    extern __shared__ __align__(16) __nv_bfloat16 smp[];

    const int tid  = threadIdx.x;
    const int lane = tid & 31;
    const int wid  = tid >> 5;
    const int wm   = wid >> 1;        // 0..3
    const int wn   = wid & 1;         // 0..1

    const int b  = blockIdx.z;
    const int m0 = blockIdx.y * 128;
    const int n0 = blockIdx.x * 128;
    const __nv_bfloat16* At = g_At;
    const __nv_bfloat16* Xb = g_Xt + (size_t)b * N_G * KP;
    float* Cp = g_logits + (size_t)b * M_G * N_G;

    __nv_bfloat16* Abuf[2] = {smp,              smp + 2 * TILE_ELEMS};
    __nv_bfloat16* Bbuf[2] = {smp + TILE_ELEMS, smp + 3 * TILE_ELEMS};

    float acc[2][8][4];
#pragma unroll
    for (int mt = 0; mt < 2; mt++)
#pragma unroll
        for (int nt = 0; nt < 8; nt++)
#pragma unroll
            for (int r = 0; r < 4; r++) acc[mt][nt][r] = 0.f;

    uint4 ra[4], rb[4];
    const uint4 zq = make_uint4(0u, 0u, 0u, 0u);
    int rowc[4], kcc[4];
#pragma unroll
    for (int i = 0; i < 4; i++) {
        const int ch = tid + i * 256;
        rowc[i] = ch >> 3;
        kcc[i]  = ch & 7;
    }

    // ldmatrix lane address offsets (derived from verified R10 fragment map)
    const int m_off  = (lane & 7) + ((lane >> 3) & 1) * 8;
    const int ka_off = (lane >> 4) * 8;
    const int n_off  = (lane & 7) + (lane >> 4) * 8;
    const int kb_off = ((lane >> 3) & 1) * 8;

    uint32_t aLane[2][2], bLane[2][4];
#pragma unroll
    for (int buf = 0; buf < 2; buf++) {
#pragma unroll
        for (int mt = 0; mt < 2; mt++)
            aLane[buf][mt] = smem_u32(
                Abuf[buf] + (wm * 32 + mt * 16 + m_off) * RSTRIDE + ka_off);
#pragma unroll
        for (int np = 0; np < 4; np++)
            bLane[buf][np] = smem_u32(
                Bbuf[buf] + (wn * 64 + np * 16 + n_off) * RSTRIDE + kb_off);
    }

    auto LDG_STAGE = [&](int s) {
        const int k0 = s * KS;
#pragma unroll
        for (int i = 0; i < 4; i++) {
            const int m = m0 + rowc[i];
            ra[i] = (m < M_G)
                ? *reinterpret_cast<const uint4*>(At + (size_t)m * KP + k0 + kcc[i] * 8)
                : zq;
            const int n = n0 + rowc[i];
            rb[i] = (n < N_G)
                ? *reinterpret_cast<const uint4*>(Xb + (size_t)n * KP + k0 + kcc[i] * 8)
                : zq;
        }
    };
    auto STS_STAGE = [&](int buf) {
#pragma unroll
        for (int i = 0; i < 4; i++) {
            const int off = rowc[i] * RSTRIDE + kcc[i] * 8;
            *reinterpret_cast<uint4*>(Abuf[buf] + off) = ra[i];
            *reinterpret_cast<uint4*>(Bbuf[buf] + off) = rb[i];
        }
    };

    auto COMPUTE = [&](int s) {
        const int buf = s & 1;
#pragma unroll
        for (int kk = 0; kk < 4; kk++) {
            const uint32_t kb = kk * 32;   // 16 bf16 = 32 bytes

            uint32_t a[2][4];
#pragma unroll
            for (int mt = 0; mt < 2; mt++)
                asm volatile(
                    "ldmatrix.sync.aligned.m8n8.x4.shared.b16 {%0,%1,%2,%3}, [%4];"
                    : "=r"(a[mt][0]), "=r"(a[mt][1]), "=r"(a[mt][2]), "=r"(a[mt][3])
                    : "r"(aLane[buf][mt] + kb));

            uint32_t bf[8][2];
#pragma unroll
            for (int np = 0; np < 4; np++) {
                uint32_t r0, r1, r2, r3;
                asm volatile(
                    "ldmatrix.sync.aligned.m8n8.x4.shared.b16 {%0,%1,%2,%3}, [%4];"
                    : "=r"(r0), "=r"(r1), "=r"(r2), "=r"(r3)
                    : "r"(bLane[buf][np] + kb));
                bf[2 * np][0]     = r0;  bf[2 * np][1]     = r1;
                bf[2 * np + 1][0] = r2;  bf[2 * np + 1][1] = r3;
            }

#pragma unroll
            for (int mt = 0; mt < 2; mt++)
#pragma unroll
                for (int nt = 0; nt < 8; nt++)
                    asm volatile(
                        "mma.sync.aligned.m16n8k16.row.col.f32.bf16.bf16.f32 "
                        "{%0,%1,%2,%3}, {%4,%5,%6,%7}, {%8,%9}, {%0,%1,%2,%3};"
                        : "+f"(acc[mt][nt][0]), "+f"(acc[mt][nt][1]),
                          "+f"(acc[mt][nt][2]), "+f"(acc[mt][nt][3])
                        : "r"(a[mt][0]), "r"(a[mt][1]), "r"(a[mt][2]), "r"(a[mt][3]),
                          "r"(bf[nt][0]), "r"(bf[nt][1]));
        }
    };

    LDG_STAGE(0);
    STS_STAGE(0);
    LDG_STAGE(1);
    __syncthreads();
    for (int s = 0; s < NST; s++) {
        COMPUTE(s);
        if (s + 1 < NST) {
            STS_STAGE((s + 1) & 1);
            if (s + 2 < NST) LDG_STAGE(s + 2);
            __syncthreads();
        }
    }

    // Epilogue: D fragment -> g_logits
    const int rbase = lane >> 2;
    const int cbase = (lane & 3) * 2;
#pragma unroll
    for (int mt = 0; mt < 2; mt++) {
#pragma unroll
        for (int nt = 0; nt < 8; nt++) {
            const int row = m0 + wm * 32 + mt * 16 + rbase;
            const int col = n0 + wn * 64 + nt * 8 + cbase;
            if (col < N_G) {
                if (row < M_G)
                    *reinterpret_cast<float2*>(Cp + (size_t)row * N_G + col) =
                        make_float2(acc[mt][nt][0], acc[mt][nt][1]);
                if (row + 8 < M_G)
                    *reinterpret_cast<float2*>(Cp + (size_t)(row + 8) * N_G + col) =
                        make_float2(acc[mt][nt][2], acc[mt][nt][3]);
            }
        }
    }
}

// ---------------------------------------------------------------------------
// Kernel 2: fused tail v2 — strip-processed conv1 (width-5 strips: x window
// in registers, 9x fewer x re-reads), then per-pixel softmax + conv2.
// ---------------------------------------------------------------------------
#define NT2 256

__global__ __launch_bounds__(NT2, 3)
void fused_tail_kernel(const float* __restrict__ x,
                       const float* __restrict__ w1,
                       const float* __restrict__ w2,
                       float* __restrict__ out)
{
    __shared__ float xs[3][32][32];
    __shared__ float fs[9 * 30 * 30];
    __shared__ float w1s[9][27];
    __shared__ float w2s[9][9];

    const int bc  = blockIdx.z;
    const int b   = bc / C_OUT;
    const int c   = bc % C_OUT;
    const int ty0 = blockIdx.y * 28;
    const int tx0 = blockIdx.x * 28;
    const int tid = threadIdx.x;

    for (int e = tid; e < 243; e += NT2)
        w1s[e / 27][e % 27] = w1[(size_t)(e / 27) * (C_OUT * 27) + c * 27 + (e % 27)];
    for (int e = tid; e < 81; e += NT2)
        w2s[e / 9][e % 9] = w2[(size_t)(e / 9) * (C_OUT * 9) + c * 9 + (e % 9)];

    const float* xb = x + ((size_t)b * CIN + 3 * c) * HW;
    for (int e = tid; e < 3 * 32 * 32; e += NT2) {
        const int j  = e >> 10;
        const int r  = e & 1023;
        const int ly = r >> 5;
        const int lx = r & 31;
        const int gy = ty0 - 2 + ly;
        const int gx = tx0 - 2 + lx;
        float v = 0.f;
        if ((unsigned)gy < (unsigned)H_IMG && (unsigned)gx < (unsigned)W_IMG)
            v = xb[(size_t)j * HW + gy * W_IMG + gx];
        xs[j][ly][lx] = v;
    }
    __syncthreads();

    // Phase B: conv1+ReLU, width-5 strips. 9 i x 30 rows x 6 strips = 1620 tasks.
    for (int t = tid; t < 9 * 30 * 6; t += NT2) {
        const int i   = t / 180;
        const int r   = t - i * 180;
        const int fy  = r / 6;
        const int fx0 = (r - fy * 6) * 5;
        const int fgy = ty0 - 1 + fy;

        float acc[5] = {0.f, 0.f, 0.f, 0.f, 0.f};
        const float* wp = &w1s[i][0];
#pragma unroll
        for (int j = 0; j < 3; j++) {
#pragma unroll
            for (int kh = 0; kh < 3; kh++) {
                float xr[7];
#pragma unroll
                for (int q = 0; q < 7; q++)
                    xr[q] = xs[j][fy + kh][fx0 + q];
                const float w0 = wp[j * 9 + kh * 3 + 0];
                const float w1v = wp[j * 9 + kh * 3 + 1];
                const float w2v = wp[j * 9 + kh * 3 + 2];
#pragma unroll
                for (int px = 0; px < 5; px++)
                    acc[px] = fmaf(w0, xr[px],
                              fmaf(w1v, xr[px + 1],
                              fmaf(w2v, xr[px + 2], acc[px])));
            }
        }
        float* fsd = &fs[i * 900 + fy * 30 + fx0];
        const bool yok = (unsigned)fgy < (unsigned)H_IMG;
#pragma unroll
        for (int px = 0; px < 5; px++) {
            const int fgx = tx0 - 1 + fx0 + px;
            float v = 0.f;
            if (yok && (unsigned)fgx < (unsigned)W_IMG)
                v = fmaxf(acc[px], 0.f);
            fsd[px] = v;
        }
    }
    __syncthreads();

    // Phase C: per pixel softmax + depthwise conv2 + aggregation
    const float* lblk = g_logits + ((size_t)b * M_G + (size_t)c * KK) * N_G;
    float* ob = out + ((size_t)b * C_OUT + c) * HW;
    for (int e = tid; e < 28 * 28; e += NT2) {
        const int oy = e / 28;
        const int ox = e - oy * 28;
        const int p  = (ty0 + oy) * W_IMG + (tx0 + ox);

        float l[9];
#pragma unroll
        for (int i = 0; i < 9; i++)
            l[i] = lblk[(size_t)i * N_G + p];

        float mx = l[0];
#pragma unroll
        for (int i = 1; i < 9; i++) mx = fmaxf(mx, l[i]);
        float s = 0.f;
#pragma unroll
        for (int i = 0; i < 9; i++) {
            l[i] = __expf(l[i] - mx);
            s += l[i];
        }
        const float inv = 1.f / s;

        float acc = 0.f;
#pragma unroll
        for (int i = 0; i < 9; i++) {
            const float* fpi = &fs[i * 900 + oy * 30 + ox];
            float dw = 0.f;
#pragma unroll
            for (int kh = 0; kh < 3; kh++)
#pragma unroll
                for (int kw = 0; kw < 3; kw++)
                    dw = fmaf(w2s[i][kh * 3 + kw], fpi[kh * 30 + kw], dw);
            acc = fmaf(l[i] * inv, dw, acc);
        }
        ob[p] = acc;
    }
}

// ---------------------------------------------------------------------------
extern "C" void kernel_launch(void* const* d_in, const int* in_sizes, int n_in,
                              void* d_out, int out_size)
{
    const float* x    = nullptr;
    const float* fc_w = nullptr;
    const float* w1   = nullptr;
    const float* w2   = nullptr;
    for (int i = 0; i < n_in; i++) {
        switch (in_sizes[i]) {
            case B_SZ * CIN * HW:        x    = (const float*)d_in[i]; break;
            case C_OUT * KK * CIN:       fc_w = (const float*)d_in[i]; break;
            case KK * C_OUT * 3 * 3 * 3: w1   = (const float*)d_in[i]; break;
            case KK * C_OUT * 3 * 3:     w2   = (const float*)d_in[i]; break;
            default: break;
        }
    }
    float* out = (float*)d_out;

    cudaFuncSetAttribute(gemm_mma_kernel,
                         cudaFuncAttributeMaxDynamicSharedMemorySize,
                         DSMEM_BYTES);

    // Pack (hi/lo split)
    pack_A_kernel<<<(M_G * K_G + 255) / 256, 256>>>(fc_w);
    dim3 gx(N_G / 32, K_G / 32, B_SZ);          // 98 x 18 x 8
    pack_X_kernel<<<gx, 256>>>(x);

    // HMMA GEMM -> g_logits
    dim3 gg((N_G + 127) / 128, (M_G + 127) / 128, B_SZ);   // 25 x 14 x 8
    gemm_mma_kernel<<<gg, 256, DSMEM_BYTES>>>();

    // fused tail v2
    dim3 g2(2, 2, B_SZ * C_OUT);
    fused_tail_kernel<<<g2, NT2>>>(x, w1, w2, out);
}

// round 12
// speedup vs baseline: 5.5614x; 1.3463x over previous
#include <cuda_runtime.h>
#include <cuda_bf16.h>
#include <cstdint>

// Problem dims
#define B_SZ 8
#define CIN 576
#define C_OUT 192
#define KK 9
#define H_IMG 56
#define W_IMG 56
#define HW 3136
#define M_G 1728
#define N_G 3136
#define K_G 576
#define KP 1728              // K' = 3*576 (hi*hi + hi*lo + lo*hi)

// Scratch (device globals: referenced ONLY from device code!)
__device__ float g_logits[(size_t)B_SZ * M_G * N_G];                  // 173 MB
__device__ __nv_bfloat16 g_At[(size_t)M_G * KP];                      // 6 MB
__device__ __nv_bfloat16 g_Xt[(size_t)B_SZ * N_G * KP];               // 87 MB

__device__ __forceinline__ uint32_t smem_u32(const void* p) {
    uint32_t a;
    asm("{ .reg .u64 t; cvta.to.shared.u64 t, %1; cvt.u32.u64 %0, t; }"
        : "=r"(a) : "l"(p));
    return a;
}

// ---------------------------------------------------------------------------
// Pack A: fc_w (1728x576) fp32 -> At (1728x1728) bf16 = [hi | hi | lo]
// ---------------------------------------------------------------------------
__global__ void pack_A_kernel(const float* __restrict__ fc_w) {
    const int e = blockIdx.x * 256 + threadIdx.x;
    if (e >= M_G * K_G) return;
    const int m = e / K_G;
    const int k = e - m * K_G;
    const float a = fc_w[e];
    const __nv_bfloat16 hi = __float2bfloat16(a);
    const __nv_bfloat16 lo = __float2bfloat16(a - __bfloat162float(hi));
    __nv_bfloat16* r = g_At + (size_t)m * KP;
    r[k]        = hi;
    r[576 + k]  = hi;
    r[1152 + k] = lo;
}

// ---------------------------------------------------------------------------
// Pack X: x (8,576,3136) fp32 -> Xt (8,3136,1728) bf16 = [hi ; lo ; hi]
// ---------------------------------------------------------------------------
__global__ __launch_bounds__(256)
void pack_X_kernel(const float* __restrict__ x) {
    __shared__ float t[32][33];
    const int bz = blockIdx.z;
    const int k0 = blockIdx.y * 32;
    const int n0 = blockIdx.x * 32;
    const int tx = threadIdx.x & 31;
    const int ty = threadIdx.x >> 5;   // 0..7

    const float* xb = x + (size_t)bz * CIN * HW;
#pragma unroll
    for (int i = 0; i < 4; i++) {
        const int k = k0 + ty + i * 8;
        t[ty + i * 8][tx] = xb[(size_t)k * HW + n0 + tx];
    }
    __syncthreads();

    __nv_bfloat16* Xb = g_Xt + (size_t)bz * N_G * KP;
#pragma unroll
    for (int i = 0; i < 4; i++) {
        const int n = n0 + ty + i * 8;
        const float a = t[tx][ty + i * 8];
        const __nv_bfloat16 hi = __float2bfloat16(a);
        const __nv_bfloat16 lo = __float2bfloat16(a - __bfloat162float(hi));
        __nv_bfloat16* r = Xb + (size_t)n * KP;
        r[k0 + tx]        = hi;
        r[576 + k0 + tx]  = lo;
        r[1152 + k0 + tx] = hi;
    }
}

// ---------------------------------------------------------------------------
// HMMA GEMM, cp.async double-buffered. ldmatrix fragment mapping identical
// to R11-verified version (padded 144B rows, conflict-free, no swizzle).
// __launch_bounds__(256,2): 2 CTAs/SM hide each other's sync bubbles.
// ---------------------------------------------------------------------------
#define KS 64
#define NST 27                         // 1728/64
#define RSTRIDE 72                     // bf16 per smem row (64 + 8 pad = 144B)
#define TILE_ELEMS (128 * RSTRIDE)
#define DSMEM_ELEMS (4 * TILE_ELEMS)   // A0,B0,A1,B1
#define DSMEM_BYTES (DSMEM_ELEMS * 2 + 256)

__global__ __launch_bounds__(256, 2)
void gemm_mma_kernel()
{
    extern __shared__ __align__(16) __nv_bfloat16 smp[];

    const int tid  = threadIdx.x;
    const int lane = tid & 31;
    const int wid  = tid >> 5;
    const int wm   = wid >> 1;        // 0..3
    const int wn   = wid & 1;         // 0..1

    const int b  = blockIdx.z;
    const int m0 = blockIdx.y * 128;
    const int n0 = blockIdx.x * 128;
    const __nv_bfloat16* At = g_At;
    const __nv_bfloat16* Xb = g_Xt + (size_t)b * N_G * KP;
    float* Cp = g_logits + (size_t)b * M_G * N_G;

    __nv_bfloat16* Abuf[2] = {smp,              smp + 2 * TILE_ELEMS};
    __nv_bfloat16* Bbuf[2] = {smp + TILE_ELEMS, smp + 3 * TILE_ELEMS};

    float acc[2][8][4];
#pragma unroll
    for (int mt = 0; mt < 2; mt++)
#pragma unroll
        for (int nt = 0; nt < 8; nt++)
#pragma unroll
            for (int r = 0; r < 4; r++) acc[mt][nt][r] = 0.f;

    int rowc[4], kcc[4];
#pragma unroll
    for (int i = 0; i < 4; i++) {
        const int ch = tid + i * 256;
        rowc[i] = ch >> 3;
        kcc[i]  = ch & 7;
    }

    // ldmatrix lane address offsets (R11-verified fragment map)
    const int m_off  = (lane & 7) + ((lane >> 3) & 1) * 8;
    const int ka_off = (lane >> 4) * 8;
    const int n_off  = (lane & 7) + (lane >> 4) * 8;
    const int kb_off = ((lane >> 3) & 1) * 8;

    uint32_t aLane[2][2], bLane[2][4];
#pragma unroll
    for (int buf = 0; buf < 2; buf++) {
#pragma unroll
        for (int mt = 0; mt < 2; mt++)
            aLane[buf][mt] = smem_u32(
                Abuf[buf] + (wm * 32 + mt * 16 + m_off) * RSTRIDE + ka_off);
#pragma unroll
        for (int np = 0; np < 4; np++)
            bLane[buf][np] = smem_u32(
                Bbuf[buf] + (wn * 64 + np * 16 + n_off) * RSTRIDE + kb_off);
    }

    // cp.async stage load: 1024 A chunks + 1024 B chunks of 16B
    auto LOAD_STAGE = [&](int s) {
        const int buf = s & 1;
        const int k0  = s * KS;
        const uint32_t asm_base = smem_u32(Abuf[buf]);
        const uint32_t bsm_base = smem_u32(Bbuf[buf]);
#pragma unroll
        for (int i = 0; i < 4; i++) {
            const bool okA = (m0 + rowc[i]) < M_G;
            const __nv_bfloat16* gA =
                okA ? (At + (size_t)(m0 + rowc[i]) * KP + k0 + kcc[i] * 8) : At;
            const uint32_t dstA =
                asm_base + (uint32_t)(rowc[i] * (RSTRIDE * 2) + kcc[i] * 16);
            const int szA = okA ? 16 : 0;
            asm volatile("cp.async.cg.shared.global [%0], [%1], 16, %2;"
                         :: "r"(dstA), "l"(gA), "r"(szA));

            const bool okB = (n0 + rowc[i]) < N_G;
            const __nv_bfloat16* gB =
                okB ? (Xb + (size_t)(n0 + rowc[i]) * KP + k0 + kcc[i] * 8) : Xb;
            const uint32_t dstB =
                bsm_base + (uint32_t)(rowc[i] * (RSTRIDE * 2) + kcc[i] * 16);
            const int szB = okB ? 16 : 0;
            asm volatile("cp.async.cg.shared.global [%0], [%1], 16, %2;"
                         :: "r"(dstB), "l"(gB), "r"(szB));
        }
        asm volatile("cp.async.commit_group;" ::: "memory");
    };

    auto COMPUTE = [&](int s) {
        const int buf = s & 1;
#pragma unroll
        for (int kk = 0; kk < 4; kk++) {
            const uint32_t kb = kk * 32;   // 16 bf16 = 32 bytes

            uint32_t a[2][4];
#pragma unroll
            for (int mt = 0; mt < 2; mt++)
                asm volatile(
                    "ldmatrix.sync.aligned.m8n8.x4.shared.b16 {%0,%1,%2,%3}, [%4];"
                    : "=r"(a[mt][0]), "=r"(a[mt][1]), "=r"(a[mt][2]), "=r"(a[mt][3])
                    : "r"(aLane[buf][mt] + kb));

            uint32_t bf[8][2];
#pragma unroll
            for (int np = 0; np < 4; np++) {
                uint32_t r0, r1, r2, r3;
                asm volatile(
                    "ldmatrix.sync.aligned.m8n8.x4.shared.b16 {%0,%1,%2,%3}, [%4];"
                    : "=r"(r0), "=r"(r1), "=r"(r2), "=r"(r3)
                    : "r"(bLane[buf][np] + kb));
                bf[2 * np][0]     = r0;  bf[2 * np][1]     = r1;
                bf[2 * np + 1][0] = r2;  bf[2 * np + 1][1] = r3;
            }

#pragma unroll
            for (int mt = 0; mt < 2; mt++)
#pragma unroll
                for (int nt = 0; nt < 8; nt++)
                    asm volatile(
                        "mma.sync.aligned.m16n8k16.row.col.f32.bf16.bf16.f32 "
                        "{%0,%1,%2,%3}, {%4,%5,%6,%7}, {%8,%9}, {%0,%1,%2,%3};"
                        : "+f"(acc[mt][nt][0]), "+f"(acc[mt][nt][1]),
                          "+f"(acc[mt][nt][2]), "+f"(acc[mt][nt][3])
                        : "r"(a[mt][0]), "r"(a[mt][1]), "r"(a[mt][2]), "r"(a[mt][3]),
                          "r"(bf[nt][0]), "r"(bf[nt][1]));
        }
    };

    LOAD_STAGE(0);
    LOAD_STAGE(1);
    for (int s = 0; s < NST; s++) {
        if (s < NST - 1)
            asm volatile("cp.async.wait_group 1;" ::: "memory");
        else
            asm volatile("cp.async.wait_group 0;" ::: "memory");
        __syncthreads();
        COMPUTE(s);
        if (s + 2 < NST) {
            __syncthreads();           // all warps done reading buffer s&1
            LOAD_STAGE(s + 2);
        }
    }

    // Epilogue: D fragment -> g_logits
    const int rbase = lane >> 2;
    const int cbase = (lane & 3) * 2;
#pragma unroll
    for (int mt = 0; mt < 2; mt++) {
#pragma unroll
        for (int nt = 0; nt < 8; nt++) {
            const int row = m0 + wm * 32 + mt * 16 + rbase;
            const int col = n0 + wn * 64 + nt * 8 + cbase;
            if (col < N_G) {
                if (row < M_G)
                    *reinterpret_cast<float2*>(Cp + (size_t)row * N_G + col) =
                        make_float2(acc[mt][nt][0], acc[mt][nt][1]);
                if (row + 8 < M_G)
                    *reinterpret_cast<float2*>(Cp + (size_t)(row + 8) * N_G + col) =
                        make_float2(acc[mt][nt][2], acc[mt][nt][3]);
            }
        }
    }
}

// ---------------------------------------------------------------------------
// Kernel 2: fused tail v3 — strip conv1 with PADDED xs rows (33 floats):
// bank = (fy + 5*strip + q) mod 32, all-distinct over the warp -> conflict-free.
// ---------------------------------------------------------------------------
#define NT2 256

__global__ __launch_bounds__(NT2, 3)
void fused_tail_kernel(const float* __restrict__ x,
                       const float* __restrict__ w1,
                       const float* __restrict__ w2,
                       float* __restrict__ out)
{
    __shared__ float xs[3][32][33];     // padded rows: conflict-free strips
    __shared__ float fs[9 * 30 * 30];
    __shared__ float w1s[9][27];
    __shared__ float w2s[9][9];

    const int bc  = blockIdx.z;
    const int b   = bc / C_OUT;
    const int c   = bc % C_OUT;
    const int ty0 = blockIdx.y * 28;
    const int tx0 = blockIdx.x * 28;
    const int tid = threadIdx.x;

    for (int e = tid; e < 243; e += NT2)
        w1s[e / 27][e % 27] = w1[(size_t)(e / 27) * (C_OUT * 27) + c * 27 + (e % 27)];
    for (int e = tid; e < 81; e += NT2)
        w2s[e / 9][e % 9] = w2[(size_t)(e / 9) * (C_OUT * 9) + c * 9 + (e % 9)];

    const float* xb = x + ((size_t)b * CIN + 3 * c) * HW;
    for (int e = tid; e < 3 * 32 * 32; e += NT2) {
        const int j  = e >> 10;
        const int r  = e & 1023;
        const int ly = r >> 5;
        const int lx = r & 31;
        const int gy = ty0 - 2 + ly;
        const int gx = tx0 - 2 + lx;
        float v = 0.f;
        if ((unsigned)gy < (unsigned)H_IMG && (unsigned)gx < (unsigned)W_IMG)
            v = xb[(size_t)j * HW + gy * W_IMG + gx];
        xs[j][ly][lx] = v;
    }
    __syncthreads();

    // Phase B: conv1+ReLU, width-5 strips. 9 i x 30 rows x 6 strips = 1620 tasks.
    for (int t = tid; t < 9 * 30 * 6; t += NT2) {
        const int i   = t / 180;
        const int r   = t - i * 180;
        const int fy  = r / 6;
        const int fx0 = (r - fy * 6) * 5;
        const int fgy = ty0 - 1 + fy;

        float acc[5] = {0.f, 0.f, 0.f, 0.f, 0.f};
        const float* wp = &w1s[i][0];
#pragma unroll
        for (int j = 0; j < 3; j++) {
#pragma unroll
            for (int kh = 0; kh < 3; kh++) {
                float xr[7];
#pragma unroll
                for (int q = 0; q < 7; q++)
                    xr[q] = xs[j][fy + kh][fx0 + q];
                const float w0  = wp[j * 9 + kh * 3 + 0];
                const float w1v = wp[j * 9 + kh * 3 + 1];
                const float w2v = wp[j * 9 + kh * 3 + 2];
#pragma unroll
                for (int px = 0; px < 5; px++)
                    acc[px] = fmaf(w0, xr[px],
                              fmaf(w1v, xr[px + 1],
                              fmaf(w2v, xr[px + 2], acc[px])));
            }
        }
        float* fsd = &fs[i * 900 + fy * 30 + fx0];
        const bool yok = (unsigned)fgy < (unsigned)H_IMG;
#pragma unroll
        for (int px = 0; px < 5; px++) {
            const int fgx = tx0 - 1 + fx0 + px;
            float v = 0.f;
            if (yok && (unsigned)fgx < (unsigned)W_IMG)
                v = fmaxf(acc[px], 0.f);
            fsd[px] = v;
        }
    }
    __syncthreads();

    // Phase C: per pixel softmax + depthwise conv2 + aggregation
    const float* lblk = g_logits + ((size_t)b * M_G + (size_t)c * KK) * N_G;
    float* ob = out + ((size_t)b * C_OUT + c) * HW;
    for (int e = tid; e < 28 * 28; e += NT2) {
        const int oy = e / 28;
        const int ox = e - oy * 28;
        const int p  = (ty0 + oy) * W_IMG + (tx0 + ox);

        float l[9];
#pragma unroll
        for (int i = 0; i < 9; i++)
            l[i] = lblk[(size_t)i * N_G + p];

        float mx = l[0];
#pragma unroll
        for (int i = 1; i < 9; i++) mx = fmaxf(mx, l[i]);
        float s = 0.f;
#pragma unroll
        for (int i = 0; i < 9; i++) {
            l[i] = __expf(l[i] - mx);
            s += l[i];
        }
        const float inv = 1.f / s;

        float acc = 0.f;
#pragma unroll
        for (int i = 0; i < 9; i++) {
            const float* fpi = &fs[i * 900 + oy * 30 + ox];
            float dw = 0.f;
#pragma unroll
            for (int kh = 0; kh < 3; kh++)
#pragma unroll
                for (int kw = 0; kw < 3; kw++)
                    dw = fmaf(w2s[i][kh * 3 + kw], fpi[kh * 30 + kw], dw);
            acc = fmaf(l[i] * inv, dw, acc);
        }
        ob[p] = acc;
    }
}

// ---------------------------------------------------------------------------
extern "C" void kernel_launch(void* const* d_in, const int* in_sizes, int n_in,
                              void* d_out, int out_size)
{
    const float* x    = nullptr;
    const float* fc_w = nullptr;
    const float* w1   = nullptr;
    const float* w2   = nullptr;
    for (int i = 0; i < n_in; i++) {
        switch (in_sizes[i]) {
            case B_SZ * CIN * HW:        x    = (const float*)d_in[i]; break;
            case C_OUT * KK * CIN:       fc_w = (const float*)d_in[i]; break;
            case KK * C_OUT * 3 * 3 * 3: w1   = (const float*)d_in[i]; break;
            case KK * C_OUT * 3 * 3:     w2   = (const float*)d_in[i]; break;
            default: break;
        }
    }
    float* out = (float*)d_out;

    cudaFuncSetAttribute(gemm_mma_kernel,
                         cudaFuncAttributeMaxDynamicSharedMemorySize,
                         DSMEM_BYTES);

    // Pack (hi/lo split)
    pack_A_kernel<<<(M_G * K_G + 255) / 256, 256>>>(fc_w);
    dim3 gx(N_G / 32, K_G / 32, B_SZ);          // 98 x 18 x 8
    pack_X_kernel<<<gx, 256>>>(x);

    // HMMA GEMM -> g_logits
    dim3 gg((N_G + 127) / 128, (M_G + 127) / 128, B_SZ);   // 25 x 14 x 8
    gemm_mma_kernel<<<gg, 256, DSMEM_BYTES>>>();

    // fused tail v3
    dim3 g2(2, 2, B_SZ * C_OUT);
    fused_tail_kernel<<<g2, NT2>>>(x, w1, w2, out);
}

// round 13
// speedup vs baseline: 5.8697x; 1.0554x over previous
#include <cuda_runtime.h>
#include <cuda_bf16.h>
#include <cstdint>

// Problem dims
#define B_SZ 8
#define CIN 576
#define C_OUT 192
#define KK 9
#define H_IMG 56
#define W_IMG 56
#define HW 3136
#define M_G 1728
#define N_G 3136
#define K_G 576
#define KP 1728              // K' = 3*576 (hi*hi + hi*lo + lo*hi)

// Scratch (device globals: referenced ONLY from device code!)
__device__ float g_logits[(size_t)B_SZ * M_G * N_G];                  // 173 MB
__device__ __nv_bfloat16 g_At[(size_t)M_G * KP];                      // 6 MB
__device__ __nv_bfloat16 g_Xt[(size_t)B_SZ * N_G * KP];               // 87 MB

__device__ __forceinline__ uint32_t smem_u32(const void* p) {
    uint32_t a;
    asm("{ .reg .u64 t; cvta.to.shared.u64 t, %1; cvt.u32.u64 %0, t; }"
        : "=r"(a) : "l"(p));
    return a;
}

// ---------------------------------------------------------------------------
// Pack A: fc_w (1728x576) fp32 -> At (1728x1728) bf16 = [hi | hi | lo]
// ---------------------------------------------------------------------------
__global__ void pack_A_kernel(const float* __restrict__ fc_w) {
    const int e = blockIdx.x * 256 + threadIdx.x;
    if (e >= M_G * K_G) return;
    const int m = e / K_G;
    const int k = e - m * K_G;
    const float a = fc_w[e];
    const __nv_bfloat16 hi = __float2bfloat16(a);
    const __nv_bfloat16 lo = __float2bfloat16(a - __bfloat162float(hi));
    __nv_bfloat16* r = g_At + (size_t)m * KP;
    r[k]        = hi;
    r[576 + k]  = hi;
    r[1152 + k] = lo;
}

// ---------------------------------------------------------------------------
// Pack X: x (8,576,3136) fp32 -> Xt (8,3136,1728) bf16 = [hi ; lo ; hi]
// ---------------------------------------------------------------------------
__global__ __launch_bounds__(256)
void pack_X_kernel(const float* __restrict__ x) {
    __shared__ float t[32][33];
    const int bz = blockIdx.z;
    const int k0 = blockIdx.y * 32;
    const int n0 = blockIdx.x * 32;
    const int tx = threadIdx.x & 31;
    const int ty = threadIdx.x >> 5;   // 0..7

    const float* xb = x + (size_t)bz * CIN * HW;
#pragma unroll
    for (int i = 0; i < 4; i++) {
        const int k = k0 + ty + i * 8;
        t[ty + i * 8][tx] = xb[(size_t)k * HW + n0 + tx];
    }
    __syncthreads();

    __nv_bfloat16* Xb = g_Xt + (size_t)bz * N_G * KP;
#pragma unroll
    for (int i = 0; i < 4; i++) {
        const int n = n0 + ty + i * 8;
        const float a = t[tx][ty + i * 8];
        const __nv_bfloat16 hi = __float2bfloat16(a);
        const __nv_bfloat16 lo = __float2bfloat16(a - __bfloat162float(hi));
        __nv_bfloat16* r = Xb + (size_t)n * KP;
        r[k0 + tx]        = hi;
        r[576 + k0 + tx]  = lo;
        r[1152 + k0 + tx] = hi;
    }
}

// ---------------------------------------------------------------------------
// HMMA GEMM, cp.async 3-buffer ring: ONE __syncthreads per stage, 2-stage
// lookahead. ldmatrix mapping identical to R11/R12-verified (144B padded
// rows, conflict-free). 2 CTAs/SM (2 x 110.6KB smem).
// ---------------------------------------------------------------------------
#define KS 64
#define NST 27                         // 1728/64
#define RSTRIDE 72                     // bf16 per smem row (64 + 8 pad = 144B)
#define TILE_ELEMS (128 * RSTRIDE)
#define TILE_BYTES (TILE_ELEMS * 2)    // 18432
#define PAIR_BYTES (2 * TILE_BYTES)    // A+B per buffer = 36864
#define DSMEM_BYTES (3 * PAIR_BYTES)   // 110592

__global__ __launch_bounds__(256, 2)
void gemm_mma_kernel()
{
    extern __shared__ __align__(16) __nv_bfloat16 smp[];

    const int tid  = threadIdx.x;
    const int lane = tid & 31;
    const int wid  = tid >> 5;
    const int wm   = wid >> 1;        // 0..3
    const int wn   = wid & 1;         // 0..1

    const int b  = blockIdx.z;
    const int m0 = blockIdx.y * 128;
    const int n0 = blockIdx.x * 128;
    const __nv_bfloat16* At = g_At;
    const __nv_bfloat16* Xb = g_Xt + (size_t)b * N_G * KP;
    float* Cp = g_logits + (size_t)b * M_G * N_G;

    const uint32_t smA0 = smem_u32(smp);               // A of buffer 0
    const uint32_t smB0 = smA0 + TILE_BYTES;           // B of buffer 0

    float acc[2][8][4];
#pragma unroll
    for (int mt = 0; mt < 2; mt++)
#pragma unroll
        for (int nt = 0; nt < 8; nt++)
#pragma unroll
            for (int r = 0; r < 4; r++) acc[mt][nt][r] = 0.f;

    int rowc[4], kcc[4];
#pragma unroll
    for (int i = 0; i < 4; i++) {
        const int ch = tid + i * 256;
        rowc[i] = ch >> 3;
        kcc[i]  = ch & 7;
    }

    // ldmatrix lane address offsets for buffer 0 (verified fragment map)
    const int m_off  = (lane & 7) + ((lane >> 3) & 1) * 8;
    const int ka_off = (lane >> 4) * 8;
    const int n_off  = (lane & 7) + (lane >> 4) * 8;
    const int kb_off = ((lane >> 3) & 1) * 8;

    uint32_t aLane0[2], bLane0[4];
#pragma unroll
    for (int mt = 0; mt < 2; mt++)
        aLane0[mt] = smA0 + ((wm * 32 + mt * 16 + m_off) * RSTRIDE + ka_off) * 2;
#pragma unroll
    for (int np = 0; np < 4; np++)
        bLane0[np] = smB0 + ((wn * 64 + np * 16 + n_off) * RSTRIDE + kb_off) * 2;

    // cp.async stage load into ring buffer s%3
    auto LOAD_STAGE = [&](int s) {
        const uint32_t boff = (uint32_t)(s % 3) * PAIR_BYTES;
        const int k0 = s * KS;
#pragma unroll
        for (int i = 0; i < 4; i++) {
            const bool okA = (m0 + rowc[i]) < M_G;
            const __nv_bfloat16* gA =
                okA ? (At + (size_t)(m0 + rowc[i]) * KP + k0 + kcc[i] * 8) : At;
            const uint32_t dstA =
                smA0 + boff + (uint32_t)(rowc[i] * (RSTRIDE * 2) + kcc[i] * 16);
            const int szA = okA ? 16 : 0;
            asm volatile("cp.async.cg.shared.global [%0], [%1], 16, %2;"
                         :: "r"(dstA), "l"(gA), "r"(szA));

            const bool okB = (n0 + rowc[i]) < N_G;
            const __nv_bfloat16* gB =
                okB ? (Xb + (size_t)(n0 + rowc[i]) * KP + k0 + kcc[i] * 8) : Xb;
            const uint32_t dstB =
                smB0 + boff + (uint32_t)(rowc[i] * (RSTRIDE * 2) + kcc[i] * 16);
            const int szB = okB ? 16 : 0;
            asm volatile("cp.async.cg.shared.global [%0], [%1], 16, %2;"
                         :: "r"(dstB), "l"(gB), "r"(szB));
        }
        asm volatile("cp.async.commit_group;" ::: "memory");
    };

    auto COMPUTE = [&](int s) {
        const uint32_t boff = (uint32_t)(s % 3) * PAIR_BYTES;
#pragma unroll
        for (int kk = 0; kk < 4; kk++) {
            const uint32_t kb = boff + kk * 32;   // 16 bf16 = 32 bytes

            uint32_t a[2][4];
#pragma unroll
            for (int mt = 0; mt < 2; mt++)
                asm volatile(
                    "ldmatrix.sync.aligned.m8n8.x4.shared.b16 {%0,%1,%2,%3}, [%4];"
                    : "=r"(a[mt][0]), "=r"(a[mt][1]), "=r"(a[mt][2]), "=r"(a[mt][3])
                    : "r"(aLane0[mt] + kb));

            uint32_t bf[8][2];
#pragma unroll
            for (int np = 0; np < 4; np++) {
                uint32_t r0, r1, r2, r3;
                asm volatile(
                    "ldmatrix.sync.aligned.m8n8.x4.shared.b16 {%0,%1,%2,%3}, [%4];"
                    : "=r"(r0), "=r"(r1), "=r"(r2), "=r"(r3)
                    : "r"(bLane0[np] + kb));
                bf[2 * np][0]     = r0;  bf[2 * np][1]     = r1;
                bf[2 * np + 1][0] = r2;  bf[2 * np + 1][1] = r3;
            }

#pragma unroll
            for (int mt = 0; mt < 2; mt++)
#pragma unroll
                for (int nt = 0; nt < 8; nt++)
                    asm volatile(
                        "mma.sync.aligned.m16n8k16.row.col.f32.bf16.bf16.f32 "
                        "{%0,%1,%2,%3}, {%4,%5,%6,%7}, {%8,%9}, {%0,%1,%2,%3};"
                        : "+f"(acc[mt][nt][0]), "+f"(acc[mt][nt][1]),
                          "+f"(acc[mt][nt][2]), "+f"(acc[mt][nt][3])
                        : "r"(a[mt][0]), "r"(a[mt][1]), "r"(a[mt][2]), "r"(a[mt][3]),
                          "r"(bf[nt][0]), "r"(bf[nt][1]));
        }
    };

    // 3-buffer ring: one sync per stage.
    // Hazard: LOAD(s+2) writes buf (s+2)%3 = (s-1)%3, last read in
    // COMPUTE(s-1); the sync at top of stage s orders them.
    LOAD_STAGE(0);
    LOAD_STAGE(1);
    for (int s = 0; s < NST; s++) {
        if (s + 1 < NST)
            asm volatile("cp.async.wait_group 1;" ::: "memory");
        else
            asm volatile("cp.async.wait_group 0;" ::: "memory");
        __syncthreads();
        COMPUTE(s);
        if (s + 2 < NST) LOAD_STAGE(s + 2);
    }

    // Epilogue: D fragment -> g_logits
    const int rbase = lane >> 2;
    const int cbase = (lane & 3) * 2;
#pragma unroll
    for (int mt = 0; mt < 2; mt++) {
#pragma unroll
        for (int nt = 0; nt < 8; nt++) {
            const int row = m0 + wm * 32 + mt * 16 + rbase;
            const int col = n0 + wn * 64 + nt * 8 + cbase;
            if (col < N_G) {
                if (row < M_G)
                    *reinterpret_cast<float2*>(Cp + (size_t)row * N_G + col) =
                        make_float2(acc[mt][nt][0], acc[mt][nt][1]);
                if (row + 8 < M_G)
                    *reinterpret_cast<float2*>(Cp + (size_t)(row + 8) * N_G + col) =
                        make_float2(acc[mt][nt][2], acc[mt][nt][3]);
            }
        }
    }
}

// ---------------------------------------------------------------------------
// Kernel 2: fused tail (R12-verified math) with 4 CTAs/SM (reg cap 64).
// ---------------------------------------------------------------------------
#define NT2 256

__global__ __launch_bounds__(NT2, 4)
void fused_tail_kernel(const float* __restrict__ x,
                       const float* __restrict__ w1,
                       const float* __restrict__ w2,
                       float* __restrict__ out)
{
    __shared__ float xs[3][32][33];     // padded rows: conflict-free strips
    __shared__ float fs[9 * 30 * 30];
    __shared__ float w1s[9][27];
    __shared__ float w2s[9][9];

    const int bc  = blockIdx.z;
    const int b   = bc / C_OUT;
    const int c   = bc % C_OUT;
    const int ty0 = blockIdx.y * 28;
    const int tx0 = blockIdx.x * 28;
    const int tid = threadIdx.x;

    for (int e = tid; e < 243; e += NT2)
        w1s[e / 27][e % 27] = w1[(size_t)(e / 27) * (C_OUT * 27) + c * 27 + (e % 27)];
    for (int e = tid; e < 81; e += NT2)
        w2s[e / 9][e % 9] = w2[(size_t)(e / 9) * (C_OUT * 9) + c * 9 + (e % 9)];

    const float* xb = x + ((size_t)b * CIN + 3 * c) * HW;
    for (int e = tid; e < 3 * 32 * 32; e += NT2) {
        const int j  = e >> 10;
        const int r  = e & 1023;
        const int ly = r >> 5;
        const int lx = r & 31;
        const int gy = ty0 - 2 + ly;
        const int gx = tx0 - 2 + lx;
        float v = 0.f;
        if ((unsigned)gy < (unsigned)H_IMG && (unsigned)gx < (unsigned)W_IMG)
            v = xb[(size_t)j * HW + gy * W_IMG + gx];
        xs[j][ly][lx] = v;
    }
    __syncthreads();

    // Phase B: conv1+ReLU, width-5 strips (conflict-free with padded xs).
    for (int t = tid; t < 9 * 30 * 6; t += NT2) {
        const int i   = t / 180;
        const int r   = t - i * 180;
        const int fy  = r / 6;
        const int fx0 = (r - fy * 6) * 5;
        const int fgy = ty0 - 1 + fy;

        float acc[5] = {0.f, 0.f, 0.f, 0.f, 0.f};
        const float* wp = &w1s[i][0];
#pragma unroll
        for (int j = 0; j < 3; j++) {
#pragma unroll
            for (int kh = 0; kh < 3; kh++) {
                float xr[7];
#pragma unroll
                for (int q = 0; q < 7; q++)
                    xr[q] = xs[j][fy + kh][fx0 + q];
                const float w0  = wp[j * 9 + kh * 3 + 0];
                const float w1v = wp[j * 9 + kh * 3 + 1];
                const float w2v = wp[j * 9 + kh * 3 + 2];
#pragma unroll
                for (int px = 0; px < 5; px++)
                    acc[px] = fmaf(w0, xr[px],
                              fmaf(w1v, xr[px + 1],
                              fmaf(w2v, xr[px + 2], acc[px])));
            }
        }
        float* fsd = &fs[i * 900 + fy * 30 + fx0];
        const bool yok = (unsigned)fgy < (unsigned)H_IMG;
#pragma unroll
        for (int px = 0; px < 5; px++) {
            const int fgx = tx0 - 1 + fx0 + px;
            float v = 0.f;
            if (yok && (unsigned)fgx < (unsigned)W_IMG)
                v = fmaxf(acc[px], 0.f);
            fsd[px] = v;
        }
    }
    __syncthreads();

    // Phase C: per pixel softmax + depthwise conv2 + aggregation
    const float* lblk = g_logits + ((size_t)b * M_G + (size_t)c * KK) * N_G;
    float* ob = out + ((size_t)b * C_OUT + c) * HW;
    for (int e = tid; e < 28 * 28; e += NT2) {
        const int oy = e / 28;
        const int ox = e - oy * 28;
        const int p  = (ty0 + oy) * W_IMG + (tx0 + ox);

        float l[9];
#pragma unroll
        for (int i = 0; i < 9; i++)
            l[i] = lblk[(size_t)i * N_G + p];

        float mx = l[0];
#pragma unroll
        for (int i = 1; i < 9; i++) mx = fmaxf(mx, l[i]);
        float s = 0.f;
#pragma unroll
        for (int i = 0; i < 9; i++) {
            l[i] = __expf(l[i] - mx);
            s += l[i];
        }
        const float inv = 1.f / s;

        float acc = 0.f;
#pragma unroll
        for (int i = 0; i < 9; i++) {
            const float* fpi = &fs[i * 900 + oy * 30 + ox];
            float dw = 0.f;
#pragma unroll
            for (int kh = 0; kh < 3; kh++)
#pragma unroll
                for (int kw = 0; kw < 3; kw++)
                    dw = fmaf(w2s[i][kh * 3 + kw], fpi[kh * 30 + kw], dw);
            acc = fmaf(l[i] * inv, dw, acc);
        }
        ob[p] = acc;
    }
}

// ---------------------------------------------------------------------------
extern "C" void kernel_launch(void* const* d_in, const int* in_sizes, int n_in,
                              void* d_out, int out_size)
{
    const float* x    = nullptr;
    const float* fc_w = nullptr;
    const float* w1   = nullptr;
    const float* w2   = nullptr;
    for (int i = 0; i < n_in; i++) {
        switch (in_sizes[i]) {
            case B_SZ * CIN * HW:        x    = (const float*)d_in[i]; break;
            case C_OUT * KK * CIN:       fc_w = (const float*)d_in[i]; break;
            case KK * C_OUT * 3 * 3 * 3: w1   = (const float*)d_in[i]; break;
            case KK * C_OUT * 3 * 3:     w2   = (const float*)d_in[i]; break;
            default: break;
        }
    }
    float* out = (float*)d_out;

    cudaFuncSetAttribute(gemm_mma_kernel,
                         cudaFuncAttributeMaxDynamicSharedMemorySize,
                         DSMEM_BYTES);

    // Pack (hi/lo split)
    pack_A_kernel<<<(M_G * K_G + 255) / 256, 256>>>(fc_w);
    dim3 gx(N_G / 32, K_G / 32, B_SZ);          // 98 x 18 x 8
    pack_X_kernel<<<gx, 256>>>(x);

    // HMMA GEMM -> g_logits
    dim3 gg((N_G + 127) / 128, (M_G + 127) / 128, B_SZ);   // 25 x 14 x 8
    gemm_mma_kernel<<<gg, 256, DSMEM_BYTES>>>();

    // fused tail
    dim3 g2(2, 2, B_SZ * C_OUT);
    fused_tail_kernel<<<g2, NT2>>>(x, w1, w2, out);
}

// round 14
// speedup vs baseline: 6.6209x; 1.1280x over previous
#include <cuda_runtime.h>
#include <cuda_bf16.h>
#include <cstdint>

// Problem dims
#define B_SZ 8
#define CIN 576
#define C_OUT 192
#define KK 9
#define H_IMG 56
#define W_IMG 56
#define HW 3136
#define M_G 1728
#define N_G 3136
#define K_G 576
#define KP 1728              // K' = 3*576 (hi*hi + hi*lo + lo*hi)

// Scratch (device globals: referenced ONLY from device code!)
__device__ float g_logits[(size_t)B_SZ * M_G * N_G];                  // 173 MB
__device__ __nv_bfloat16 g_At[(size_t)M_G * KP];                      // 6 MB
__device__ __nv_bfloat16 g_Xt[(size_t)B_SZ * N_G * KP];               // 87 MB

__device__ __forceinline__ uint32_t smem_u32(const void* p) {
    uint32_t a;
    asm("{ .reg .u64 t; cvta.to.shared.u64 t, %1; cvt.u32.u64 %0, t; }"
        : "=r"(a) : "l"(p));
    return a;
}

// ---------------------------------------------------------------------------
// Pack A: fc_w (1728x576) fp32 -> At (1728x1728) bf16 = [hi | hi | lo]
// ---------------------------------------------------------------------------
__global__ void pack_A_kernel(const float* __restrict__ fc_w) {
    const int e = blockIdx.x * 256 + threadIdx.x;
    if (e >= M_G * K_G) return;
    const int m = e / K_G;
    const int k = e - m * K_G;
    const float a = fc_w[e];
    const __nv_bfloat16 hi = __float2bfloat16(a);
    const __nv_bfloat16 lo = __float2bfloat16(a - __bfloat162float(hi));
    __nv_bfloat16* r = g_At + (size_t)m * KP;
    r[k]        = hi;
    r[576 + k]  = hi;
    r[1152 + k] = lo;
}

// ---------------------------------------------------------------------------
// Pack X: x (8,576,3136) fp32 -> Xt (8,3136,1728) bf16 = [hi ; lo ; hi]
// bf16x2 stores: each lane writes 4B, 64B->128B-class segments.
// ---------------------------------------------------------------------------
__global__ __launch_bounds__(256)
void pack_X_kernel(const float* __restrict__ x) {
    __shared__ float t[32][33];
    const int bz = blockIdx.z;
    const int k0 = blockIdx.y * 32;
    const int n0 = blockIdx.x * 32;
    const int tx = threadIdx.x & 31;
    const int ty = threadIdx.x >> 5;   // 0..7

    const float* xb = x + (size_t)bz * CIN * HW;
#pragma unroll
    for (int i = 0; i < 4; i++) {
        const int k = k0 + ty + i * 8;
        t[ty + i * 8][tx] = xb[(size_t)k * HW + n0 + tx];   // t[k_local][n_local]
    }
    __syncthreads();

    __nv_bfloat16* Xb = g_Xt + (size_t)bz * N_G * KP;
    const int kp2 = threadIdx.x & 15;      // k-pair 0..15
    const int nl  = threadIdx.x >> 4;      // 0..15
#pragma unroll
    for (int i = 0; i < 2; i++) {
        const int n_local = nl + i * 16;
        const int n = n0 + n_local;
        const float a0 = t[2 * kp2][n_local];
        const float a1 = t[2 * kp2 + 1][n_local];
        const __nv_bfloat16 h0 = __float2bfloat16(a0);
        const __nv_bfloat16 l0 = __float2bfloat16(a0 - __bfloat162float(h0));
        const __nv_bfloat16 h1 = __float2bfloat16(a1);
        const __nv_bfloat16 l1 = __float2bfloat16(a1 - __bfloat162float(h1));
        __nv_bfloat162 hh; hh.x = h0; hh.y = h1;
        __nv_bfloat162 ll; ll.x = l0; ll.y = l1;
        __nv_bfloat16* base = Xb + (size_t)n * KP + k0 + 2 * kp2;
        *reinterpret_cast<__nv_bfloat162*>(base)        = hh;
        *reinterpret_cast<__nv_bfloat162*>(base + 576)  = ll;
        *reinterpret_cast<__nv_bfloat162*>(base + 1152) = hh;
    }
}

// ---------------------------------------------------------------------------
// HMMA GEMM, cp.async 3-buffer ring (R13-verified, unchanged).
// ---------------------------------------------------------------------------
#define KS 64
#define NST 27                         // 1728/64
#define RSTRIDE 72                     // bf16 per smem row (64 + 8 pad = 144B)
#define TILE_ELEMS (128 * RSTRIDE)
#define TILE_BYTES (TILE_ELEMS * 2)    // 18432
#define PAIR_BYTES (2 * TILE_BYTES)    // 36864
#define DSMEM_BYTES (3 * PAIR_BYTES)   // 110592

__global__ __launch_bounds__(256, 2)
void gemm_mma_kernel()
{
    extern __shared__ __align__(16) __nv_bfloat16 smp[];

    const int tid  = threadIdx.x;
    const int lane = tid & 31;
    const int wid  = tid >> 5;
    const int wm   = wid >> 1;
    const int wn   = wid & 1;

    const int b  = blockIdx.z;
    const int m0 = blockIdx.y * 128;
    const int n0 = blockIdx.x * 128;
    const __nv_bfloat16* At = g_At;
    const __nv_bfloat16* Xb = g_Xt + (size_t)b * N_G * KP;
    float* Cp = g_logits + (size_t)b * M_G * N_G;

    const uint32_t smA0 = smem_u32(smp);
    const uint32_t smB0 = smA0 + TILE_BYTES;

    float acc[2][8][4];
#pragma unroll
    for (int mt = 0; mt < 2; mt++)
#pragma unroll
        for (int nt = 0; nt < 8; nt++)
#pragma unroll
            for (int r = 0; r < 4; r++) acc[mt][nt][r] = 0.f;

    int rowc[4], kcc[4];
#pragma unroll
    for (int i = 0; i < 4; i++) {
        const int ch = tid + i * 256;
        rowc[i] = ch >> 3;
        kcc[i]  = ch & 7;
    }

    const int m_off  = (lane & 7) + ((lane >> 3) & 1) * 8;
    const int ka_off = (lane >> 4) * 8;
    const int n_off  = (lane & 7) + (lane >> 4) * 8;
    const int kb_off = ((lane >> 3) & 1) * 8;

    uint32_t aLane0[2], bLane0[4];
#pragma unroll
    for (int mt = 0; mt < 2; mt++)
        aLane0[mt] = smA0 + ((wm * 32 + mt * 16 + m_off) * RSTRIDE + ka_off) * 2;
#pragma unroll
    for (int np = 0; np < 4; np++)
        bLane0[np] = smB0 + ((wn * 64 + np * 16 + n_off) * RSTRIDE + kb_off) * 2;

    auto LOAD_STAGE = [&](int s) {
        const uint32_t boff = (uint32_t)(s % 3) * PAIR_BYTES;
        const int k0 = s * KS;
#pragma unroll
        for (int i = 0; i < 4; i++) {
            const bool okA = (m0 + rowc[i]) < M_G;
            const __nv_bfloat16* gA =
                okA ? (At + (size_t)(m0 + rowc[i]) * KP + k0 + kcc[i] * 8) : At;
            const uint32_t dstA =
                smA0 + boff + (uint32_t)(rowc[i] * (RSTRIDE * 2) + kcc[i] * 16);
            const int szA = okA ? 16 : 0;
            asm volatile("cp.async.cg.shared.global [%0], [%1], 16, %2;"
                         :: "r"(dstA), "l"(gA), "r"(szA));

            const bool okB = (n0 + rowc[i]) < N_G;
            const __nv_bfloat16* gB =
                okB ? (Xb + (size_t)(n0 + rowc[i]) * KP + k0 + kcc[i] * 8) : Xb;
            const uint32_t dstB =
                smB0 + boff + (uint32_t)(rowc[i] * (RSTRIDE * 2) + kcc[i] * 16);
            const int szB = okB ? 16 : 0;
            asm volatile("cp.async.cg.shared.global [%0], [%1], 16, %2;"
                         :: "r"(dstB), "l"(gB), "r"(szB));
        }
        asm volatile("cp.async.commit_group;" ::: "memory");
    };

    auto COMPUTE = [&](int s) {
        const uint32_t boff = (uint32_t)(s % 3) * PAIR_BYTES;
#pragma unroll
        for (int kk = 0; kk < 4; kk++) {
            const uint32_t kb = boff + kk * 32;

            uint32_t a[2][4];
#pragma unroll
            for (int mt = 0; mt < 2; mt++)
                asm volatile(
                    "ldmatrix.sync.aligned.m8n8.x4.shared.b16 {%0,%1,%2,%3}, [%4];"
                    : "=r"(a[mt][0]), "=r"(a[mt][1]), "=r"(a[mt][2]), "=r"(a[mt][3])
                    : "r"(aLane0[mt] + kb));

            uint32_t bf[8][2];
#pragma unroll
            for (int np = 0; np < 4; np++) {
                uint32_t r0, r1, r2, r3;
                asm volatile(
                    "ldmatrix.sync.aligned.m8n8.x4.shared.b16 {%0,%1,%2,%3}, [%4];"
                    : "=r"(r0), "=r"(r1), "=r"(r2), "=r"(r3)
                    : "r"(bLane0[np] + kb));
                bf[2 * np][0]     = r0;  bf[2 * np][1]     = r1;
                bf[2 * np + 1][0] = r2;  bf[2 * np + 1][1] = r3;
            }

#pragma unroll
            for (int mt = 0; mt < 2; mt++)
#pragma unroll
                for (int nt = 0; nt < 8; nt++)
                    asm volatile(
                        "mma.sync.aligned.m16n8k16.row.col.f32.bf16.bf16.f32 "
                        "{%0,%1,%2,%3}, {%4,%5,%6,%7}, {%8,%9}, {%0,%1,%2,%3};"
                        : "+f"(acc[mt][nt][0]), "+f"(acc[mt][nt][1]),
                          "+f"(acc[mt][nt][2]), "+f"(acc[mt][nt][3])
                        : "r"(a[mt][0]), "r"(a[mt][1]), "r"(a[mt][2]), "r"(a[mt][3]),
                          "r"(bf[nt][0]), "r"(bf[nt][1]));
        }
    };

    LOAD_STAGE(0);
    LOAD_STAGE(1);
    for (int s = 0; s < NST; s++) {
        if (s + 1 < NST)
            asm volatile("cp.async.wait_group 1;" ::: "memory");
        else
            asm volatile("cp.async.wait_group 0;" ::: "memory");
        __syncthreads();
        COMPUTE(s);
        if (s + 2 < NST) LOAD_STAGE(s + 2);
    }

    const int rbase = lane >> 2;
    const int cbase = (lane & 3) * 2;
#pragma unroll
    for (int mt = 0; mt < 2; mt++) {
#pragma unroll
        for (int nt = 0; nt < 8; nt++) {
            const int row = m0 + wm * 32 + mt * 16 + rbase;
            const int col = n0 + wn * 64 + nt * 8 + cbase;
            if (col < N_G) {
                if (row < M_G)
                    *reinterpret_cast<float2*>(Cp + (size_t)row * N_G + col) =
                        make_float2(acc[mt][nt][0], acc[mt][nt][1]);
                if (row + 8 < M_G)
                    *reinterpret_cast<float2*>(Cp + (size_t)(row + 8) * N_G + col) =
                        make_float2(acc[mt][nt][2], acc[mt][nt][3]);
            }
        }
    }
}

// ---------------------------------------------------------------------------
// Kernel 2: fused tail v4 — phase B width-5 strips (R12-verified), phase C
// width-2 pixel strips with float2 window/logit/output accesses.
// ---------------------------------------------------------------------------
#define NT2 256

__global__ __launch_bounds__(NT2, 3)
void fused_tail_kernel(const float* __restrict__ x,
                       const float* __restrict__ w1,
                       const float* __restrict__ w2,
                       float* __restrict__ out)
{
    __shared__ float xs[3][32][33];     // padded rows: conflict-free strips
    __shared__ float fs[9 * 30 * 30];
    __shared__ float w1s[9][27];
    __shared__ float w2s[9][9];

    const int bc  = blockIdx.z;
    const int b   = bc / C_OUT;
    const int c   = bc % C_OUT;
    const int ty0 = blockIdx.y * 28;
    const int tx0 = blockIdx.x * 28;
    const int tid = threadIdx.x;

    for (int e = tid; e < 243; e += NT2)
        w1s[e / 27][e % 27] = w1[(size_t)(e / 27) * (C_OUT * 27) + c * 27 + (e % 27)];
    for (int e = tid; e < 81; e += NT2)
        w2s[e / 9][e % 9] = w2[(size_t)(e / 9) * (C_OUT * 9) + c * 9 + (e % 9)];

    const float* xb = x + ((size_t)b * CIN + 3 * c) * HW;
    for (int e = tid; e < 3 * 32 * 32; e += NT2) {
        const int j  = e >> 10;
        const int r  = e & 1023;
        const int ly = r >> 5;
        const int lx = r & 31;
        const int gy = ty0 - 2 + ly;
        const int gx = tx0 - 2 + lx;
        float v = 0.f;
        if ((unsigned)gy < (unsigned)H_IMG && (unsigned)gx < (unsigned)W_IMG)
            v = xb[(size_t)j * HW + gy * W_IMG + gx];
        xs[j][ly][lx] = v;
    }
    __syncthreads();

    // Phase B: conv1+ReLU, width-5 strips (conflict-free with padded xs).
    for (int t = tid; t < 9 * 30 * 6; t += NT2) {
        const int i   = t / 180;
        const int r   = t - i * 180;
        const int fy  = r / 6;
        const int fx0 = (r - fy * 6) * 5;
        const int fgy = ty0 - 1 + fy;

        float acc[5] = {0.f, 0.f, 0.f, 0.f, 0.f};
        const float* wp = &w1s[i][0];
#pragma unroll
        for (int j = 0; j < 3; j++) {
#pragma unroll
            for (int kh = 0; kh < 3; kh++) {
                float xr[7];
#pragma unroll
                for (int q = 0; q < 7; q++)
                    xr[q] = xs[j][fy + kh][fx0 + q];
                const float w0  = wp[j * 9 + kh * 3 + 0];
                const float w1v = wp[j * 9 + kh * 3 + 1];
                const float w2v = wp[j * 9 + kh * 3 + 2];
#pragma unroll
                for (int px = 0; px < 5; px++)
                    acc[px] = fmaf(w0, xr[px],
                              fmaf(w1v, xr[px + 1],
                              fmaf(w2v, xr[px + 2], acc[px])));
            }
        }
        float* fsd = &fs[i * 900 + fy * 30 + fx0];
        const bool yok = (unsigned)fgy < (unsigned)H_IMG;
#pragma unroll
        for (int px = 0; px < 5; px++) {
            const int fgx = tx0 - 1 + fx0 + px;
            float v = 0.f;
            if (yok && (unsigned)fgx < (unsigned)W_IMG)
                v = fmaxf(acc[px], 0.f);
            fsd[px] = v;
        }
    }
    __syncthreads();

    // Phase C: width-2 pixel strips. 28 rows x 14 strips = 392 tasks.
    const float* lblk = g_logits + ((size_t)b * M_G + (size_t)c * KK) * N_G;
    float* ob = out + ((size_t)b * C_OUT + c) * HW;
    for (int e = tid; e < 28 * 14; e += NT2) {
        const int oy  = e / 14;
        const int ox0 = (e - oy * 14) * 2;
        const int p   = (ty0 + oy) * W_IMG + (tx0 + ox0);   // even -> f2 aligned

        float2 l2[9];
#pragma unroll
        for (int i = 0; i < 9; i++)
            l2[i] = *reinterpret_cast<const float2*>(lblk + (size_t)i * N_G + p);

        float mx0 = l2[0].x, mx1 = l2[0].y;
#pragma unroll
        for (int i = 1; i < 9; i++) {
            mx0 = fmaxf(mx0, l2[i].x);
            mx1 = fmaxf(mx1, l2[i].y);
        }
        float s0 = 0.f, s1 = 0.f;
#pragma unroll
        for (int i = 0; i < 9; i++) {
            l2[i].x = __expf(l2[i].x - mx0);  s0 += l2[i].x;
            l2[i].y = __expf(l2[i].y - mx1);  s1 += l2[i].y;
        }
        const float inv0 = 1.f / s0;
        const float inv1 = 1.f / s1;

        float acc0 = 0.f, acc1 = 0.f;
#pragma unroll
        for (int i = 0; i < 9; i++) {
            const float* fpi = &fs[i * 900 + oy * 30 + ox0];   // even idx -> f2 ok
            float dw0 = 0.f, dw1 = 0.f;
#pragma unroll
            for (int kh = 0; kh < 3; kh++) {
                const float2 wlo = *reinterpret_cast<const float2*>(fpi + kh * 30);
                const float2 whi = *reinterpret_cast<const float2*>(fpi + kh * 30 + 2);
                const float wv0 = w2s[i][kh * 3 + 0];
                const float wv1 = w2s[i][kh * 3 + 1];
                const float wv2 = w2s[i][kh * 3 + 2];
                dw0 = fmaf(wv0, wlo.x, fmaf(wv1, wlo.y, fmaf(wv2, whi.x, dw0)));
                dw1 = fmaf(wv0, wlo.y, fmaf(wv1, whi.x, fmaf(wv2, whi.y, dw1)));
            }
            acc0 = fmaf(l2[i].x * inv0, dw0, acc0);
            acc1 = fmaf(l2[i].y * inv1, dw1, acc1);
        }
        *reinterpret_cast<float2*>(ob + p) = make_float2(acc0, acc1);
    }
}

// ---------------------------------------------------------------------------
extern "C" void kernel_launch(void* const* d_in, const int* in_sizes, int n_in,
                              void* d_out, int out_size)
{
    const float* x    = nullptr;
    const float* fc_w = nullptr;
    const float* w1   = nullptr;
    const float* w2   = nullptr;
    for (int i = 0; i < n_in; i++) {
        switch (in_sizes[i]) {
            case B_SZ * CIN * HW:        x    = (const float*)d_in[i]; break;
            case C_OUT * KK * CIN:       fc_w = (const float*)d_in[i]; break;
            case KK * C_OUT * 3 * 3 * 3: w1   = (const float*)d_in[i]; break;
            case KK * C_OUT * 3 * 3:     w2   = (const float*)d_in[i]; break;
            default: break;
        }
    }
    float* out = (float*)d_out;

    cudaFuncSetAttribute(gemm_mma_kernel,
                         cudaFuncAttributeMaxDynamicSharedMemorySize,
                         DSMEM_BYTES);

    // Pack (hi/lo split)
    pack_A_kernel<<<(M_G * K_G + 255) / 256, 256>>>(fc_w);
    dim3 gx(N_G / 32, K_G / 32, B_SZ);          // 98 x 18 x 8
    pack_X_kernel<<<gx, 256>>>(x);

    // HMMA GEMM -> g_logits
    dim3 gg((N_G + 127) / 128, (M_G + 127) / 128, B_SZ);   // 25 x 14 x 8
    gemm_mma_kernel<<<gg, 256, DSMEM_BYTES>>>();

    // fused tail v4
    dim3 g2(2, 2, B_SZ * C_OUT);
    fused_tail_kernel<<<g2, NT2>>>(x, w1, w2, out);
}

// round 15
// speedup vs baseline: 8.0427x; 1.2147x over previous
#include <cuda_runtime.h>
#include <cuda_fp16.h>
#include <cstdint>

// Problem dims
#define B_SZ 8
#define CIN 576
#define C_OUT 192
#define KK 9
#define H_IMG 56
#define W_IMG 56
#define HW 3136
#define M_G 1728
#define N_G 3136
#define K_G 576
#define KP 1152              // K' = 2*576: fp16 2-term (Ah·Xh + Ah·Xl)

// Scratch (device globals: referenced ONLY from device code!)
__device__ float g_logits[(size_t)B_SZ * M_G * N_G];                  // 173 MB
__device__ __half g_At[(size_t)M_G * KP];                             // 4 MB
__device__ __half g_Xt[(size_t)B_SZ * N_G * KP];                      // 58 MB

__device__ __forceinline__ uint32_t smem_u32(const void* p) {
    uint32_t a;
    asm("{ .reg .u64 t; cvta.to.shared.u64 t, %1; cvt.u32.u64 %0, t; }"
        : "=r"(a) : "l"(p));
    return a;
}

// ---------------------------------------------------------------------------
// Pack A: fc_w (1728x576) fp32 -> At (1728x1152) fp16 = [hi | hi]
// ---------------------------------------------------------------------------
__global__ void pack_A_kernel(const float* __restrict__ fc_w) {
    const int e = blockIdx.x * 256 + threadIdx.x;
    if (e >= M_G * K_G) return;
    const int m = e / K_G;
    const int k = e - m * K_G;
    const __half hi = __float2half(fc_w[e]);
    __half* r = g_At + (size_t)m * KP;
    r[k]       = hi;
    r[576 + k] = hi;
}

// ---------------------------------------------------------------------------
// Pack X: x (8,576,3136) fp32 -> Xt (8,3136,1152) fp16 = [hi ; lo]
// half2 stores (4B per lane).
// ---------------------------------------------------------------------------
__global__ __launch_bounds__(256)
void pack_X_kernel(const float* __restrict__ x) {
    __shared__ float t[32][33];
    const int bz = blockIdx.z;
    const int k0 = blockIdx.y * 32;
    const int n0 = blockIdx.x * 32;
    const int tx = threadIdx.x & 31;
    const int ty = threadIdx.x >> 5;   // 0..7

    const float* xb = x + (size_t)bz * CIN * HW;
#pragma unroll
    for (int i = 0; i < 4; i++) {
        const int k = k0 + ty + i * 8;
        t[ty + i * 8][tx] = xb[(size_t)k * HW + n0 + tx];   // t[k_local][n_local]
    }
    __syncthreads();

    __half* Xb = g_Xt + (size_t)bz * N_G * KP;
    const int kp2 = threadIdx.x & 15;      // k-pair 0..15
    const int nl  = threadIdx.x >> 4;      // 0..15
#pragma unroll
    for (int i = 0; i < 2; i++) {
        const int n_local = nl + i * 16;
        const int n = n0 + n_local;
        const float a0 = t[2 * kp2][n_local];
        const float a1 = t[2 * kp2 + 1][n_local];
        const __half h0 = __float2half(a0);
        const __half l0 = __float2half(a0 - __half2float(h0));
        const __half h1 = __float2half(a1);
        const __half l1 = __float2half(a1 - __half2float(h1));
        __half2 hh; hh.x = h0; hh.y = h1;
        __half2 ll; ll.x = l0; ll.y = l1;
        __half* base = Xb + (size_t)n * KP + k0 + 2 * kp2;
        *reinterpret_cast<__half2*>(base)       = hh;
        *reinterpret_cast<__half2*>(base + 576) = ll;
    }
}

// ---------------------------------------------------------------------------
// HMMA GEMM (fp16 in, fp32 accum), cp.async 3-buffer ring — R13/R14-verified
// structure, K' = 1152 (18 stages).
// ---------------------------------------------------------------------------
#define KS 64
#define NST 18                         // 1152/64
#define RSTRIDE 72                     // fp16 per smem row (64 + 8 pad = 144B)
#define TILE_ELEMS (128 * RSTRIDE)
#define TILE_BYTES (TILE_ELEMS * 2)    // 18432
#define PAIR_BYTES (2 * TILE_BYTES)    // 36864
#define DSMEM_BYTES (3 * PAIR_BYTES)   // 110592

__global__ __launch_bounds__(256, 2)
void gemm_mma_kernel()
{
    extern __shared__ __align__(16) __half smp[];

    const int tid  = threadIdx.x;
    const int lane = tid & 31;
    const int wid  = tid >> 5;
    const int wm   = wid >> 1;
    const int wn   = wid & 1;

    const int b  = blockIdx.z;
    const int m0 = blockIdx.y * 128;
    const int n0 = blockIdx.x * 128;
    const __half* At = g_At;
    const __half* Xb = g_Xt + (size_t)b * N_G * KP;
    float* Cp = g_logits + (size_t)b * M_G * N_G;

    const uint32_t smA0 = smem_u32(smp);
    const uint32_t smB0 = smA0 + TILE_BYTES;

    float acc[2][8][4];
#pragma unroll
    for (int mt = 0; mt < 2; mt++)
#pragma unroll
        for (int nt = 0; nt < 8; nt++)
#pragma unroll
            for (int r = 0; r < 4; r++) acc[mt][nt][r] = 0.f;

    int rowc[4], kcc[4];
#pragma unroll
    for (int i = 0; i < 4; i++) {
        const int ch = tid + i * 256;
        rowc[i] = ch >> 3;
        kcc[i]  = ch & 7;
    }

    const int m_off  = (lane & 7) + ((lane >> 3) & 1) * 8;
    const int ka_off = (lane >> 4) * 8;
    const int n_off  = (lane & 7) + (lane >> 4) * 8;
    const int kb_off = ((lane >> 3) & 1) * 8;

    uint32_t aLane0[2], bLane0[4];
#pragma unroll
    for (int mt = 0; mt < 2; mt++)
        aLane0[mt] = smA0 + ((wm * 32 + mt * 16 + m_off) * RSTRIDE + ka_off) * 2;
#pragma unroll
    for (int np = 0; np < 4; np++)
        bLane0[np] = smB0 + ((wn * 64 + np * 16 + n_off) * RSTRIDE + kb_off) * 2;

    auto LOAD_STAGE = [&](int s) {
        const uint32_t boff = (uint32_t)(s % 3) * PAIR_BYTES;
        const int k0 = s * KS;
#pragma unroll
        for (int i = 0; i < 4; i++) {
            const bool okA = (m0 + rowc[i]) < M_G;
            const __half* gA =
                okA ? (At + (size_t)(m0 + rowc[i]) * KP + k0 + kcc[i] * 8) : At;
            const uint32_t dstA =
                smA0 + boff + (uint32_t)(rowc[i] * (RSTRIDE * 2) + kcc[i] * 16);
            const int szA = okA ? 16 : 0;
            asm volatile("cp.async.cg.shared.global [%0], [%1], 16, %2;"
                         :: "r"(dstA), "l"(gA), "r"(szA));

            const bool okB = (n0 + rowc[i]) < N_G;
            const __half* gB =
                okB ? (Xb + (size_t)(n0 + rowc[i]) * KP + k0 + kcc[i] * 8) : Xb;
            const uint32_t dstB =
                smB0 + boff + (uint32_t)(rowc[i] * (RSTRIDE * 2) + kcc[i] * 16);
            const int szB = okB ? 16 : 0;
            asm volatile("cp.async.cg.shared.global [%0], [%1], 16, %2;"
                         :: "r"(dstB), "l"(gB), "r"(szB));
        }
        asm volatile("cp.async.commit_group;" ::: "memory");
    };

    auto COMPUTE = [&](int s) {
        const uint32_t boff = (uint32_t)(s % 3) * PAIR_BYTES;
#pragma unroll
        for (int kk = 0; kk < 4; kk++) {
            const uint32_t kb = boff + kk * 32;

            uint32_t a[2][4];
#pragma unroll
            for (int mt = 0; mt < 2; mt++)
                asm volatile(
                    "ldmatrix.sync.aligned.m8n8.x4.shared.b16 {%0,%1,%2,%3}, [%4];"
                    : "=r"(a[mt][0]), "=r"(a[mt][1]), "=r"(a[mt][2]), "=r"(a[mt][3])
                    : "r"(aLane0[mt] + kb));

            uint32_t bf[8][2];
#pragma unroll
            for (int np = 0; np < 4; np++) {
                uint32_t r0, r1, r2, r3;
                asm volatile(
                    "ldmatrix.sync.aligned.m8n8.x4.shared.b16 {%0,%1,%2,%3}, [%4];"
                    : "=r"(r0), "=r"(r1), "=r"(r2), "=r"(r3)
                    : "r"(bLane0[np] + kb));
                bf[2 * np][0]     = r0;  bf[2 * np][1]     = r1;
                bf[2 * np + 1][0] = r2;  bf[2 * np + 1][1] = r3;
            }

#pragma unroll
            for (int mt = 0; mt < 2; mt++)
#pragma unroll
                for (int nt = 0; nt < 8; nt++)
                    asm volatile(
                        "mma.sync.aligned.m16n8k16.row.col.f32.f16.f16.f32 "
                        "{%0,%1,%2,%3}, {%4,%5,%6,%7}, {%8,%9}, {%0,%1,%2,%3};"
                        : "+f"(acc[mt][nt][0]), "+f"(acc[mt][nt][1]),
                          "+f"(acc[mt][nt][2]), "+f"(acc[mt][nt][3])
                        : "r"(a[mt][0]), "r"(a[mt][1]), "r"(a[mt][2]), "r"(a[mt][3]),
                          "r"(bf[nt][0]), "r"(bf[nt][1]));
        }
    };

    LOAD_STAGE(0);
    LOAD_STAGE(1);
    for (int s = 0; s < NST; s++) {
        if (s + 1 < NST)
            asm volatile("cp.async.wait_group 1;" ::: "memory");
        else
            asm volatile("cp.async.wait_group 0;" ::: "memory");
        __syncthreads();
        COMPUTE(s);
        if (s + 2 < NST) LOAD_STAGE(s + 2);
    }

    const int rbase = lane >> 2;
    const int cbase = (lane & 3) * 2;
#pragma unroll
    for (int mt = 0; mt < 2; mt++) {
#pragma unroll
        for (int nt = 0; nt < 8; nt++) {
            const int row = m0 + wm * 32 + mt * 16 + rbase;
            const int col = n0 + wn * 64 + nt * 8 + cbase;
            if (col < N_G) {
                if (row < M_G)
                    *reinterpret_cast<float2*>(Cp + (size_t)row * N_G + col) =
                        make_float2(acc[mt][nt][0], acc[mt][nt][1]);
                if (row + 8 < M_G)
                    *reinterpret_cast<float2*>(Cp + (size_t)(row + 8) * N_G + col) =
                        make_float2(acc[mt][nt][2], acc[mt][nt][3]);
            }
        }
    }
}

// ---------------------------------------------------------------------------
// Kernel 2: fused tail v4 (R14-verified, unchanged).
// ---------------------------------------------------------------------------
#define NT2 256

__global__ __launch_bounds__(NT2, 3)
void fused_tail_kernel(const float* __restrict__ x,
                       const float* __restrict__ w1,
                       const float* __restrict__ w2,
                       float* __restrict__ out)
{
    __shared__ float xs[3][32][33];     // padded rows: conflict-free strips
    __shared__ float fs[9 * 30 * 30];
    __shared__ float w1s[9][27];
    __shared__ float w2s[9][9];

    const int bc  = blockIdx.z;
    const int b   = bc / C_OUT;
    const int c   = bc % C_OUT;
    const int ty0 = blockIdx.y * 28;
    const int tx0 = blockIdx.x * 28;
    const int tid = threadIdx.x;

    for (int e = tid; e < 243; e += NT2)
        w1s[e / 27][e % 27] = w1[(size_t)(e / 27) * (C_OUT * 27) + c * 27 + (e % 27)];
    for (int e = tid; e < 81; e += NT2)
        w2s[e / 9][e % 9] = w2[(size_t)(e / 9) * (C_OUT * 9) + c * 9 + (e % 9)];

    const float* xb = x + ((size_t)b * CIN + 3 * c) * HW;
    for (int e = tid; e < 3 * 32 * 32; e += NT2) {
        const int j  = e >> 10;
        const int r  = e & 1023;
        const int ly = r >> 5;
        const int lx = r & 31;
        const int gy = ty0 - 2 + ly;
        const int gx = tx0 - 2 + lx;
        float v = 0.f;
        if ((unsigned)gy < (unsigned)H_IMG && (unsigned)gx < (unsigned)W_IMG)
            v = xb[(size_t)j * HW + gy * W_IMG + gx];
        xs[j][ly][lx] = v;
    }
    __syncthreads();

    // Phase B: conv1+ReLU, width-5 strips (conflict-free with padded xs).
    for (int t = tid; t < 9 * 30 * 6; t += NT2) {
        const int i   = t / 180;
        const int r   = t - i * 180;
        const int fy  = r / 6;
        const int fx0 = (r - fy * 6) * 5;
        const int fgy = ty0 - 1 + fy;

        float acc[5] = {0.f, 0.f, 0.f, 0.f, 0.f};
        const float* wp = &w1s[i][0];
#pragma unroll
        for (int j = 0; j < 3; j++) {
#pragma unroll
            for (int kh = 0; kh < 3; kh++) {
                float xr[7];
#pragma unroll
                for (int q = 0; q < 7; q++)
                    xr[q] = xs[j][fy + kh][fx0 + q];
                const float w0  = wp[j * 9 + kh * 3 + 0];
                const float w1v = wp[j * 9 + kh * 3 + 1];
                const float w2v = wp[j * 9 + kh * 3 + 2];
#pragma unroll
                for (int px = 0; px < 5; px++)
                    acc[px] = fmaf(w0, xr[px],
                              fmaf(w1v, xr[px + 1],
                              fmaf(w2v, xr[px + 2], acc[px])));
            }
        }
        float* fsd = &fs[i * 900 + fy * 30 + fx0];
        const bool yok = (unsigned)fgy < (unsigned)H_IMG;
#pragma unroll
        for (int px = 0; px < 5; px++) {
            const int fgx = tx0 - 1 + fx0 + px;
            float v = 0.f;
            if (yok && (unsigned)fgx < (unsigned)W_IMG)
                v = fmaxf(acc[px], 0.f);
            fsd[px] = v;
        }
    }
    __syncthreads();

    // Phase C: width-2 pixel strips. 28 rows x 14 strips = 392 tasks.
    const float* lblk = g_logits + ((size_t)b * M_G + (size_t)c * KK) * N_G;
    float* ob = out + ((size_t)b * C_OUT + c) * HW;
    for (int e = tid; e < 28 * 14; e += NT2) {
        const int oy  = e / 14;
        const int ox0 = (e - oy * 14) * 2;
        const int p   = (ty0 + oy) * W_IMG + (tx0 + ox0);   // even -> f2 aligned

        float2 l2[9];
#pragma unroll
        for (int i = 0; i < 9; i++)
            l2[i] = *reinterpret_cast<const float2*>(lblk + (size_t)i * N_G + p);

        float mx0 = l2[0].x, mx1 = l2[0].y;
#pragma unroll
        for (int i = 1; i < 9; i++) {
            mx0 = fmaxf(mx0, l2[i].x);
            mx1 = fmaxf(mx1, l2[i].y);
        }
        float s0 = 0.f, s1 = 0.f;
#pragma unroll
        for (int i = 0; i < 9; i++) {
            l2[i].x = __expf(l2[i].x - mx0);  s0 += l2[i].x;
            l2[i].y = __expf(l2[i].y - mx1);  s1 += l2[i].y;
        }
        const float inv0 = 1.f / s0;
        const float inv1 = 1.f / s1;

        float acc0 = 0.f, acc1 = 0.f;
#pragma unroll
        for (int i = 0; i < 9; i++) {
            const float* fpi = &fs[i * 900 + oy * 30 + ox0];   // even idx -> f2 ok
            float dw0 = 0.f, dw1 = 0.f;
#pragma unroll
            for (int kh = 0; kh < 3; kh++) {
                const float2 wlo = *reinterpret_cast<const float2*>(fpi + kh * 30);
                const float2 whi = *reinterpret_cast<const float2*>(fpi + kh * 30 + 2);
                const float wv0 = w2s[i][kh * 3 + 0];
                const float wv1 = w2s[i][kh * 3 + 1];
                const float wv2 = w2s[i][kh * 3 + 2];
                dw0 = fmaf(wv0, wlo.x, fmaf(wv1, wlo.y, fmaf(wv2, whi.x, dw0)));
                dw1 = fmaf(wv0, wlo.y, fmaf(wv1, whi.x, fmaf(wv2, whi.y, dw1)));
            }
            acc0 = fmaf(l2[i].x * inv0, dw0, acc0);
            acc1 = fmaf(l2[i].y * inv1, dw1, acc1);
        }
        *reinterpret_cast<float2*>(ob + p) = make_float2(acc0, acc1);
    }
}

// ---------------------------------------------------------------------------
extern "C" void kernel_launch(void* const* d_in, const int* in_sizes, int n_in,
                              void* d_out, int out_size)
{
    const float* x    = nullptr;
    const float* fc_w = nullptr;
    const float* w1   = nullptr;
    const float* w2   = nullptr;
    for (int i = 0; i < n_in; i++) {
        switch (in_sizes[i]) {
            case B_SZ * CIN * HW:        x    = (const float*)d_in[i]; break;
            case C_OUT * KK * CIN:       fc_w = (const float*)d_in[i]; break;
            case KK * C_OUT * 3 * 3 * 3: w1   = (const float*)d_in[i]; break;
            case KK * C_OUT * 3 * 3:     w2   = (const float*)d_in[i]; break;
            default: break;
        }
    }
    float* out = (float*)d_out;

    cudaFuncSetAttribute(gemm_mma_kernel,
                         cudaFuncAttributeMaxDynamicSharedMemorySize,
                         DSMEM_BYTES);

    // Pack (fp16, 2-term: A=[hi|hi], X=[hi;lo])
    pack_A_kernel<<<(M_G * K_G + 255) / 256, 256>>>(fc_w);
    dim3 gx(N_G / 32, K_G / 32, B_SZ);          // 98 x 18 x 8
    pack_X_kernel<<<gx, 256>>>(x);

    // HMMA GEMM -> g_logits
    dim3 gg((N_G + 127) / 128, (M_G + 127) / 128, B_SZ);   // 25 x 14 x 8
    gemm_mma_kernel<<<gg, 256, DSMEM_BYTES>>>();

    // fused tail v4
    dim3 g2(2, 2, B_SZ * C_OUT);
    fused_tail_kernel<<<g2, NT2>>>(x, w1, w2, out);
}

// round 16
// speedup vs baseline: 10.2485x; 1.2743x over previous
#include <cuda_runtime.h>
#include <cuda_fp16.h>
#include <cstdint>

// Problem dims
#define B_SZ 8
#define CIN 576
#define C_OUT 192
#define KK 9
#define H_IMG 56
#define W_IMG 56
#define HW 3136
#define M_G 1728
#define N_G 3136
#define K_G 576
#define KP 576               // K' = 576: plain fp16 single-term GEMM

// Scratch (device globals: referenced ONLY from device code!)
__device__ float g_logits[(size_t)B_SZ * M_G * N_G];                  // 173 MB
__device__ __half g_At[(size_t)M_G * KP];                             // 2 MB
__device__ __half g_Xt[(size_t)B_SZ * N_G * KP];                      // 29 MB

__device__ __forceinline__ uint32_t smem_u32(const void* p) {
    uint32_t a;
    asm("{ .reg .u64 t; cvta.to.shared.u64 t, %1; cvt.u32.u64 %0, t; }"
        : "=r"(a) : "l"(p));
    return a;
}

// ---------------------------------------------------------------------------
// Pack A: fc_w (1728x576) fp32 -> At (1728x576) fp16
// ---------------------------------------------------------------------------
__global__ void pack_A_kernel(const float* __restrict__ fc_w) {
    const int e = blockIdx.x * 256 + threadIdx.x;
    if (e >= M_G * K_G) return;
    g_At[e] = __float2half(fc_w[e]);
}

// ---------------------------------------------------------------------------
// Pack X: x (8,576,3136) fp32 -> Xt (8,3136,576) fp16 (transposed), half2 st.
// ---------------------------------------------------------------------------
__global__ __launch_bounds__(256)
void pack_X_kernel(const float* __restrict__ x) {
    __shared__ float t[32][33];
    const int bz = blockIdx.z;
    const int k0 = blockIdx.y * 32;
    const int n0 = blockIdx.x * 32;
    const int tx = threadIdx.x & 31;
    const int ty = threadIdx.x >> 5;   // 0..7

    const float* xb = x + (size_t)bz * CIN * HW;
#pragma unroll
    for (int i = 0; i < 4; i++) {
        const int k = k0 + ty + i * 8;
        t[ty + i * 8][tx] = xb[(size_t)k * HW + n0 + tx];   // t[k_local][n_local]
    }
    __syncthreads();

    __half* Xb = g_Xt + (size_t)bz * N_G * KP;
    const int kp2 = threadIdx.x & 15;      // k-pair 0..15
    const int nl  = threadIdx.x >> 4;      // 0..15
#pragma unroll
    for (int i = 0; i < 2; i++) {
        const int n_local = nl + i * 16;
        const int n = n0 + n_local;
        __half2 hh;
        hh.x = __float2half(t[2 * kp2][n_local]);
        hh.y = __float2half(t[2 * kp2 + 1][n_local]);
        *reinterpret_cast<__half2*>(Xb + (size_t)n * KP + k0 + 2 * kp2) = hh;
    }
}

// ---------------------------------------------------------------------------
// HMMA GEMM (fp16 in, fp32 accum), cp.async 3-buffer ring — verified
// structure, K' = 576 (9 stages).
// ---------------------------------------------------------------------------
#define KS 64
#define NST 9                          // 576/64
#define RSTRIDE 72                     // fp16 per smem row (64 + 8 pad = 144B)
#define TILE_ELEMS (128 * RSTRIDE)
#define TILE_BYTES (TILE_ELEMS * 2)    // 18432
#define PAIR_BYTES (2 * TILE_BYTES)    // 36864
#define DSMEM_BYTES (3 * PAIR_BYTES)   // 110592

__global__ __launch_bounds__(256, 2)
void gemm_mma_kernel()
{
    extern __shared__ __align__(16) __half smp[];

    const int tid  = threadIdx.x;
    const int lane = tid & 31;
    const int wid  = tid >> 5;
    const int wm   = wid >> 1;
    const int wn   = wid & 1;

    const int b  = blockIdx.z;
    const int m0 = blockIdx.y * 128;
    const int n0 = blockIdx.x * 128;
    const __half* At = g_At;
    const __half* Xb = g_Xt + (size_t)b * N_G * KP;
    float* Cp = g_logits + (size_t)b * M_G * N_G;

    const uint32_t smA0 = smem_u32(smp);
    const uint32_t smB0 = smA0 + TILE_BYTES;

    float acc[2][8][4];
#pragma unroll
    for (int mt = 0; mt < 2; mt++)
#pragma unroll
        for (int nt = 0; nt < 8; nt++)
#pragma unroll
            for (int r = 0; r < 4; r++) acc[mt][nt][r] = 0.f;

    int rowc[4], kcc[4];
#pragma unroll
    for (int i = 0; i < 4; i++) {
        const int ch = tid + i * 256;
        rowc[i] = ch >> 3;
        kcc[i]  = ch & 7;
    }

    const int m_off  = (lane & 7) + ((lane >> 3) & 1) * 8;
    const int ka_off = (lane >> 4) * 8;
    const int n_off  = (lane & 7) + (lane >> 4) * 8;
    const int kb_off = ((lane >> 3) & 1) * 8;

    uint32_t aLane0[2], bLane0[4];
#pragma unroll
    for (int mt = 0; mt < 2; mt++)
        aLane0[mt] = smA0 + ((wm * 32 + mt * 16 + m_off) * RSTRIDE + ka_off) * 2;
#pragma unroll
    for (int np = 0; np < 4; np++)
        bLane0[np] = smB0 + ((wn * 64 + np * 16 + n_off) * RSTRIDE + kb_off) * 2;

    auto LOAD_STAGE = [&](int s) {
        const uint32_t boff = (uint32_t)(s % 3) * PAIR_BYTES;
        const int k0 = s * KS;
#pragma unroll
        for (int i = 0; i < 4; i++) {
            const bool okA = (m0 + rowc[i]) < M_G;
            const __half* gA =
                okA ? (At + (size_t)(m0 + rowc[i]) * KP + k0 + kcc[i] * 8) : At;
            const uint32_t dstA =
                smA0 + boff + (uint32_t)(rowc[i] * (RSTRIDE * 2) + kcc[i] * 16);
            const int szA = okA ? 16 : 0;
            asm volatile("cp.async.cg.shared.global [%0], [%1], 16, %2;"
                         :: "r"(dstA), "l"(gA), "r"(szA));

            const bool okB = (n0 + rowc[i]) < N_G;
            const __half* gB =
                okB ? (Xb + (size_t)(n0 + rowc[i]) * KP + k0 + kcc[i] * 8) : Xb;
            const uint32_t dstB =
                smB0 + boff + (uint32_t)(rowc[i] * (RSTRIDE * 2) + kcc[i] * 16);
            const int szB = okB ? 16 : 0;
            asm volatile("cp.async.cg.shared.global [%0], [%1], 16, %2;"
                         :: "r"(dstB), "l"(gB), "r"(szB));
        }
        asm volatile("cp.async.commit_group;" ::: "memory");
    };

    auto COMPUTE = [&](int s) {
        const uint32_t boff = (uint32_t)(s % 3) * PAIR_BYTES;
#pragma unroll
        for (int kk = 0; kk < 4; kk++) {
            const uint32_t kb = boff + kk * 32;

            uint32_t a[2][4];
#pragma unroll
            for (int mt = 0; mt < 2; mt++)
                asm volatile(
                    "ldmatrix.sync.aligned.m8n8.x4.shared.b16 {%0,%1,%2,%3}, [%4];"
                    : "=r"(a[mt][0]), "=r"(a[mt][1]), "=r"(a[mt][2]), "=r"(a[mt][3])
                    : "r"(aLane0[mt] + kb));

            uint32_t bf[8][2];
#pragma unroll
            for (int np = 0; np < 4; np++) {
                uint32_t r0, r1, r2, r3;
                asm volatile(
                    "ldmatrix.sync.aligned.m8n8.x4.shared.b16 {%0,%1,%2,%3}, [%4];"
                    : "=r"(r0), "=r"(r1), "=r"(r2), "=r"(r3)
                    : "r"(bLane0[np] + kb));
                bf[2 * np][0]     = r0;  bf[2 * np][1]     = r1;
                bf[2 * np + 1][0] = r2;  bf[2 * np + 1][1] = r3;
            }

#pragma unroll
            for (int mt = 0; mt < 2; mt++)
#pragma unroll
                for (int nt = 0; nt < 8; nt++)
                    asm volatile(
                        "mma.sync.aligned.m16n8k16.row.col.f32.f16.f16.f32 "
                        "{%0,%1,%2,%3}, {%4,%5,%6,%7}, {%8,%9}, {%0,%1,%2,%3};"
                        : "+f"(acc[mt][nt][0]), "+f"(acc[mt][nt][1]),
                          "+f"(acc[mt][nt][2]), "+f"(acc[mt][nt][3])
                        : "r"(a[mt][0]), "r"(a[mt][1]), "r"(a[mt][2]), "r"(a[mt][3]),
                          "r"(bf[nt][0]), "r"(bf[nt][1]));
        }
    };

    LOAD_STAGE(0);
    LOAD_STAGE(1);
    for (int s = 0; s < NST; s++) {
        if (s + 1 < NST)
            asm volatile("cp.async.wait_group 1;" ::: "memory");
        else
            asm volatile("cp.async.wait_group 0;" ::: "memory");
        __syncthreads();
        COMPUTE(s);
        if (s + 2 < NST) LOAD_STAGE(s + 2);
    }

    const int rbase = lane >> 2;
    const int cbase = (lane & 3) * 2;
#pragma unroll
    for (int mt = 0; mt < 2; mt++) {
#pragma unroll
        for (int nt = 0; nt < 8; nt++) {
            const int row = m0 + wm * 32 + mt * 16 + rbase;
            const int col = n0 + wn * 64 + nt * 8 + cbase;
            if (col < N_G) {
                if (row < M_G)
                    *reinterpret_cast<float2*>(Cp + (size_t)row * N_G + col) =
                        make_float2(acc[mt][nt][0], acc[mt][nt][1]);
                if (row + 8 < M_G)
                    *reinterpret_cast<float2*>(Cp + (size_t)(row + 8) * N_G + col) =
                        make_float2(acc[mt][nt][2], acc[mt][nt][3]);
            }
        }
    }
}

// ---------------------------------------------------------------------------
// Kernel 2: fused tail v4 (R14/R15-verified, unchanged).
// ---------------------------------------------------------------------------
#define NT2 256

__global__ __launch_bounds__(NT2, 3)
void fused_tail_kernel(const float* __restrict__ x,
                       const float* __restrict__ w1,
                       const float* __restrict__ w2,
                       float* __restrict__ out)
{
    __shared__ float xs[3][32][33];     // padded rows: conflict-free strips
    __shared__ float fs[9 * 30 * 30];
    __shared__ float w1s[9][27];
    __shared__ float w2s[9][9];

    const int bc  = blockIdx.z;
    const int b   = bc / C_OUT;
    const int c   = bc % C_OUT;
    const int ty0 = blockIdx.y * 28;
    const int tx0 = blockIdx.x * 28;
    const int tid = threadIdx.x;

    for (int e = tid; e < 243; e += NT2)
        w1s[e / 27][e % 27] = w1[(size_t)(e / 27) * (C_OUT * 27) + c * 27 + (e % 27)];
    for (int e = tid; e < 81; e += NT2)
        w2s[e / 9][e % 9] = w2[(size_t)(e / 9) * (C_OUT * 9) + c * 9 + (e % 9)];

    const float* xb = x + ((size_t)b * CIN + 3 * c) * HW;
    for (int e = tid; e < 3 * 32 * 32; e += NT2) {
        const int j  = e >> 10;
        const int r  = e & 1023;
        const int ly = r >> 5;
        const int lx = r & 31;
        const int gy = ty0 - 2 + ly;
        const int gx = tx0 - 2 + lx;
        float v = 0.f;
        if ((unsigned)gy < (unsigned)H_IMG && (unsigned)gx < (unsigned)W_IMG)
            v = xb[(size_t)j * HW + gy * W_IMG + gx];
        xs[j][ly][lx] = v;
    }
    __syncthreads();

    // Phase B: conv1+ReLU, width-5 strips (conflict-free with padded xs).
    for (int t = tid; t < 9 * 30 * 6; t += NT2) {
        const int i   = t / 180;
        const int r   = t - i * 180;
        const int fy  = r / 6;
        const int fx0 = (r - fy * 6) * 5;
        const int fgy = ty0 - 1 + fy;

        float acc[5] = {0.f, 0.f, 0.f, 0.f, 0.f};
        const float* wp = &w1s[i][0];
#pragma unroll
        for (int j = 0; j < 3; j++) {
#pragma unroll
            for (int kh = 0; kh < 3; kh++) {
                float xr[7];
#pragma unroll
                for (int q = 0; q < 7; q++)
                    xr[q] = xs[j][fy + kh][fx0 + q];
                const float w0  = wp[j * 9 + kh * 3 + 0];
                const float w1v = wp[j * 9 + kh * 3 + 1];
                const float w2v = wp[j * 9 + kh * 3 + 2];
#pragma unroll
                for (int px = 0; px < 5; px++)
                    acc[px] = fmaf(w0, xr[px],
                              fmaf(w1v, xr[px + 1],
                              fmaf(w2v, xr[px + 2], acc[px])));
            }
        }
        float* fsd = &fs[i * 900 + fy * 30 + fx0];
        const bool yok = (unsigned)fgy < (unsigned)H_IMG;
#pragma unroll
        for (int px = 0; px < 5; px++) {
            const int fgx = tx0 - 1 + fx0 + px;
            float v = 0.f;
            if (yok && (unsigned)fgx < (unsigned)W_IMG)
                v = fmaxf(acc[px], 0.f);
            fsd[px] = v;
        }
    }
    __syncthreads();

    // Phase C: width-2 pixel strips. 28 rows x 14 strips = 392 tasks.
    const float* lblk = g_logits + ((size_t)b * M_G + (size_t)c * KK) * N_G;
    float* ob = out + ((size_t)b * C_OUT + c) * HW;
    for (int e = tid; e < 28 * 14; e += NT2) {
        const int oy  = e / 14;
        const int ox0 = (e - oy * 14) * 2;
        const int p   = (ty0 + oy) * W_IMG + (tx0 + ox0);   // even -> f2 aligned

        float2 l2[9];
#pragma unroll
        for (int i = 0; i < 9; i++)
            l2[i] = *reinterpret_cast<const float2*>(lblk + (size_t)i * N_G + p);

        float mx0 = l2[0].x, mx1 = l2[0].y;
#pragma unroll
        for (int i = 1; i < 9; i++) {
            mx0 = fmaxf(mx0, l2[i].x);
            mx1 = fmaxf(mx1, l2[i].y);
        }
        float s0 = 0.f, s1 = 0.f;
#pragma unroll
        for (int i = 0; i < 9; i++) {
            l2[i].x = __expf(l2[i].x - mx0);  s0 += l2[i].x;
            l2[i].y = __expf(l2[i].y - mx1);  s1 += l2[i].y;
        }
        const float inv0 = 1.f / s0;
        const float inv1 = 1.f / s1;

        float acc0 = 0.f, acc1 = 0.f;
#pragma unroll
        for (int i = 0; i < 9; i++) {
            const float* fpi = &fs[i * 900 + oy * 30 + ox0];   // even idx -> f2 ok
            float dw0 = 0.f, dw1 = 0.f;
#pragma unroll
            for (int kh = 0; kh < 3; kh++) {
                const float2 wlo = *reinterpret_cast<const float2*>(fpi + kh * 30);
                const float2 whi = *reinterpret_cast<const float2*>(fpi + kh * 30 + 2);
                const float wv0 = w2s[i][kh * 3 + 0];
                const float wv1 = w2s[i][kh * 3 + 1];
                const float wv2 = w2s[i][kh * 3 + 2];
                dw0 = fmaf(wv0, wlo.x, fmaf(wv1, wlo.y, fmaf(wv2, whi.x, dw0)));
                dw1 = fmaf(wv0, wlo.y, fmaf(wv1, whi.x, fmaf(wv2, whi.y, dw1)));
            }
            acc0 = fmaf(l2[i].x * inv0, dw0, acc0);
            acc1 = fmaf(l2[i].y * inv1, dw1, acc1);
        }
        *reinterpret_cast<float2*>(ob + p) = make_float2(acc0, acc1);
    }
}

// ---------------------------------------------------------------------------
extern "C" void kernel_launch(void* const* d_in, const int* in_sizes, int n_in,
                              void* d_out, int out_size)
{
    const float* x    = nullptr;
    const float* fc_w = nullptr;
    const float* w1   = nullptr;
    const float* w2   = nullptr;
    for (int i = 0; i < n_in; i++) {
        switch (in_sizes[i]) {
            case B_SZ * CIN * HW:        x    = (const float*)d_in[i]; break;
            case C_OUT * KK * CIN:       fc_w = (const float*)d_in[i]; break;
            case KK * C_OUT * 3 * 3 * 3: w1   = (const float*)d_in[i]; break;
            case KK * C_OUT * 3 * 3:     w2   = (const float*)d_in[i]; break;
            default: break;
        }
    }
    float* out = (float*)d_out;

    cudaFuncSetAttribute(gemm_mma_kernel,
                         cudaFuncAttributeMaxDynamicSharedMemorySize,
                         DSMEM_BYTES);

    // Pack (plain fp16)
    pack_A_kernel<<<(M_G * K_G + 255) / 256, 256>>>(fc_w);
    dim3 gx(N_G / 32, K_G / 32, B_SZ);          // 98 x 18 x 8
    pack_X_kernel<<<gx, 256>>>(x);

    // HMMA GEMM -> g_logits
    dim3 gg((N_G + 127) / 128, (M_G + 127) / 128, B_SZ);   // 25 x 14 x 8
    gemm_mma_kernel<<<gg, 256, DSMEM_BYTES>>>();

    // fused tail v4
    dim3 g2(2, 2, B_SZ * C_OUT);
    fused_tail_kernel<<<g2, NT2>>>(x, w1, w2, out);
}